// round 6
// baseline (speedup 1.0000x reference)
#include <cuda_runtime.h>

#define RR   3
#define NN   50000
#define EE   200000
#define RN   (RR*NN)
#define RE   (RR*EE)
#define DIN  128
#define DHID 128
#define DOUT 64

// ---------------- scratch (device globals; no allocation allowed) ----------
__device__ int   g_deg_out[RN];
__device__ int   g_deg_in [RN];
__device__ float g_onorm  [RN];
__device__ float g_inorm  [RN];
__device__ int   g_rowptr [RN + 1];
__device__ int   g_pos    [RN];
__device__ int   g_colsrc [RE];
__device__ float g_Y1[(size_t)RN * DHID];   // per-relation transformed feats, layer 1
__device__ float g_H [(size_t)NN * DHID];   // hidden after relu
__device__ float g_Y2[(size_t)RN * DOUT];   // per-relation transformed feats, layer 2

// ---------------- helpers ---------------------------------------------------
__device__ __forceinline__ unsigned long long bcast2(float a) {
    unsigned long long r;
    asm("mov.b64 %0, {%1, %1};" : "=l"(r) : "r"(__float_as_uint(a)));
    return r;
}
__device__ __forceinline__ void fma2(unsigned long long& d,
                                     unsigned long long a,
                                     unsigned long long b) {
    asm("fma.rn.f32x2 %0, %1, %2, %3;" : "=l"(d) : "l"(a), "l"(b), "l"(d));
}

// ---------------- graph preprocessing ---------------------------------------
__global__ void zero_deg_kernel() {
    int i = blockIdx.x * blockDim.x + threadIdx.x;
    if (i < RN) { g_deg_out[i] = 0; g_deg_in[i] = 0; }
}

__global__ void count_deg_kernel(const int* __restrict__ src,
                                 const int* __restrict__ dst) {
    int i = blockIdx.x * blockDim.x + threadIdx.x;
    if (i >= RE) return;
    int r = i / EE;
    atomicAdd(&g_deg_out[r * NN + src[i]], 1);
    atomicAdd(&g_deg_in [r * NN + dst[i]], 1);
}

__global__ void norm_kernel() {
    int i = blockIdx.x * blockDim.x + threadIdx.x;
    if (i >= RN) return;
    int od = g_deg_out[i]; if (od < 1) od = 1;
    int id = g_deg_in [i]; if (id < 1) id = 1;
    g_onorm[i] = rsqrtf((float)od);
    g_inorm[i] = rsqrtf((float)id);
}

// Single-block exclusive scan of g_deg_in -> g_rowptr / g_pos  (RN = 150000)
__global__ void scan_kernel() {
    __shared__ int sums[1024];
    const int t = threadIdx.x;
    const int chunk = (RN + 1023) / 1024;           // 147
    int beg = t * chunk;
    int end = beg + chunk; if (end > RN) end = RN;
    if (beg > RN) beg = RN;

    int s = 0;
    for (int i = beg; i < end; i++) s += g_deg_in[i];
    sums[t] = s;
    __syncthreads();
    // Hillis-Steele inclusive scan over 1024 partials
    for (int off = 1; off < 1024; off <<= 1) {
        int v = (t >= off) ? sums[t - off] : 0;
        __syncthreads();
        sums[t] += v;
        __syncthreads();
    }
    int run = (t == 0) ? 0 : sums[t - 1];
    if (t == 1023) g_rowptr[RN] = sums[1023];
    for (int i = beg; i < end; i++) {
        g_rowptr[i] = run;
        g_pos[i]    = run;
        run += g_deg_in[i];
    }
}

__global__ void fill_csr_kernel(const int* __restrict__ src,
                                const int* __restrict__ dst) {
    int i = blockIdx.x * blockDim.x + threadIdx.x;
    if (i >= RE) return;
    int r = i / EE;
    int p = atomicAdd(&g_pos[r * NN + dst[i]], 1);
    g_colsrc[p] = src[i];
}

// ---------------- batched GEMM:  Y[r] = (onorm_r ⊙ A) @ W[r]  ----------------
// Block tile: 128 rows x BN cols, full K=128 resident in SMEM. 256 threads,
// each computing an 8 x (BN/16) register tile with packed f32x2 FMAs.
template <int BN, int LAYER>
__global__ void __launch_bounds__(256, 1)
gemm_kernel(const float* __restrict__ xin, const float* __restrict__ W) {
    extern __shared__ float sm[];
    float* As = sm;                 // [128][132]  (K-major, padded)
    float* Ws = sm + 128 * 132;     // [128][BN]

    const float* A    = (LAYER == 0) ? xin : g_H;
    float*       Yout = (LAYER == 0) ? g_Y1 : g_Y2;

    const int r    = blockIdx.y;
    const int row0 = blockIdx.x * 128;
    const int t    = threadIdx.x;

    // --- load W[r] (K x BN) straight into SMEM, float4 ---
    const float4* Wr = (const float4*)(W + (size_t)r * 128 * BN);
    #pragma unroll
    for (int i = t; i < 128 * BN / 4; i += 256) ((float4*)Ws)[i] = Wr[i];

    // --- load A tile transposed & scaled by out-norm ---
    for (int i = t; i < 128 * 32; i += 256) {
        int row = i >> 5;           // 0..127
        int k4  = i & 31;           // float4 index along K
        int grow = row0 + row;
        float4 v = make_float4(0.f, 0.f, 0.f, 0.f);
        float  s = 0.f;
        if (grow < NN) {
            v = ((const float4*)(A + (size_t)grow * 128))[k4];
            s = g_onorm[r * NN + grow];
        }
        int kb = k4 * 4;
        As[(kb + 0) * 132 + row] = v.x * s;
        As[(kb + 1) * 132 + row] = v.y * s;
        As[(kb + 2) * 132 + row] = v.z * s;
        As[(kb + 3) * 132 + row] = v.w * s;
    }
    __syncthreads();

    const int tx = t & 15;          // 16 col-groups
    const int ty = t >> 4;          // 16 row-groups
    constexpr int TN = BN / 16;     // 8 (L1) or 4 (L2) cols per thread
    constexpr int NP = TN / 2;      // f32x2 pairs

    unsigned long long acc[8][NP];
    #pragma unroll
    for (int i = 0; i < 8; i++)
        #pragma unroll
        for (int j = 0; j < NP; j++) acc[i][j] = 0ull;

    for (int k = 0; k < 128; k++) {
        const float* ak = &As[k * 132 + ty * 8];
        float4 a0 = *(const float4*)(ak);
        float4 a1 = *(const float4*)(ak + 4);
        unsigned long long aa[8];
        aa[0] = bcast2(a0.x); aa[1] = bcast2(a0.y);
        aa[2] = bcast2(a0.z); aa[3] = bcast2(a0.w);
        aa[4] = bcast2(a1.x); aa[5] = bcast2(a1.y);
        aa[6] = bcast2(a1.z); aa[7] = bcast2(a1.w);

        const ulonglong2* bk = (const ulonglong2*)&Ws[k * BN + tx * TN];
        unsigned long long bb[NP];
        #pragma unroll
        for (int j = 0; j < NP; j += 2) {
            ulonglong2 v = bk[j >> 1];
            bb[j] = v.x;
            bb[j + 1] = v.y;
        }
        #pragma unroll
        for (int i = 0; i < 8; i++)
            #pragma unroll
            for (int j = 0; j < NP; j++) fma2(acc[i][j], aa[i], bb[j]);
    }

    #pragma unroll
    for (int i = 0; i < 8; i++) {
        int grow = row0 + ty * 8 + i;
        if (grow < NN) {
            unsigned long long* dstp =
                (unsigned long long*)&Yout[((size_t)r * NN + grow) * BN + tx * TN];
            #pragma unroll
            for (int j = 0; j < NP; j++) dstp[j] = acc[i][j];
        }
    }
}

// ---------------- aggregation (gather via CSR), layer 1: relu + bias --------
__global__ void agg1_kernel(const float* __restrict__ b1) {
    int gt   = blockIdx.x * blockDim.x + threadIdx.x;
    int n    = gt >> 5;
    int lane = gt & 31;
    if (n >= NN) return;

    float4 acc = make_float4(0.f, 0.f, 0.f, 0.f);
    #pragma unroll
    for (int r = 0; r < RR; r++) {
        int key = r * NN + n;
        int beg = g_rowptr[key];
        int end = g_rowptr[key + 1];
        float4 s = make_float4(0.f, 0.f, 0.f, 0.f);
        for (int j = beg; j < end; j++) {
            int sn = g_colsrc[j];
            float4 v = *(const float4*)&g_Y1[((size_t)r * NN + sn) * DHID + lane * 4];
            s.x += v.x; s.y += v.y; s.z += v.z; s.w += v.w;
        }
        float inn = g_inorm[key];
        acc.x += inn * s.x; acc.y += inn * s.y;
        acc.z += inn * s.z; acc.w += inn * s.w;
    }
    int col = lane * 4;
    acc.x += b1[col + 0] + b1[DHID + col + 0] + b1[2 * DHID + col + 0];
    acc.y += b1[col + 1] + b1[DHID + col + 1] + b1[2 * DHID + col + 1];
    acc.z += b1[col + 2] + b1[DHID + col + 2] + b1[2 * DHID + col + 2];
    acc.w += b1[col + 3] + b1[DHID + col + 3] + b1[2 * DHID + col + 3];
    acc.x = fmaxf(acc.x, 0.f); acc.y = fmaxf(acc.y, 0.f);
    acc.z = fmaxf(acc.z, 0.f); acc.w = fmaxf(acc.w, 0.f);
    *(float4*)&g_H[(size_t)n * DHID + col] = acc;
}

// ---------------- aggregation layer 2: bias, write output -------------------
__global__ void agg2_kernel(const float* __restrict__ b2,
                            float* __restrict__ out) {
    int gt   = blockIdx.x * blockDim.x + threadIdx.x;
    int n    = gt >> 5;
    int lane = gt & 31;
    if (n >= NN) return;

    float2 acc = make_float2(0.f, 0.f);
    #pragma unroll
    for (int r = 0; r < RR; r++) {
        int key = r * NN + n;
        int beg = g_rowptr[key];
        int end = g_rowptr[key + 1];
        float2 s = make_float2(0.f, 0.f);
        for (int j = beg; j < end; j++) {
            int sn = g_colsrc[j];
            float2 v = *(const float2*)&g_Y2[((size_t)r * NN + sn) * DOUT + lane * 2];
            s.x += v.x; s.y += v.y;
        }
        float inn = g_inorm[key];
        acc.x += inn * s.x; acc.y += inn * s.y;
    }
    int col = lane * 2;
    acc.x += b2[col + 0] + b2[DOUT + col + 0] + b2[2 * DOUT + col + 0];
    acc.y += b2[col + 1] + b2[DOUT + col + 1] + b2[2 * DOUT + col + 1];
    *(float2*)&out[(size_t)n * DOUT + col] = acc;
}

// ---------------- launch -----------------------------------------------------
extern "C" void kernel_launch(void* const* d_in, const int* in_sizes, int n_in,
                              void* d_out, int out_size) {
    const float* x   = (const float*)d_in[0];
    const float* W1  = (const float*)d_in[1];
    const float* b1  = (const float*)d_in[2];
    const float* W2  = (const float*)d_in[3];
    const float* b2  = (const float*)d_in[4];
    const int*   src = (const int*)d_in[5];
    const int*   dst = (const int*)d_in[6];
    float*       out = (float*)d_out;

    const int SMEM1 = (128 * 132 + 128 * 128) * 4;   // 133120
    const int SMEM2 = (128 * 132 + 128 * 64) * 4;    // 100352
    cudaFuncSetAttribute(gemm_kernel<128, 0>,
                         cudaFuncAttributeMaxDynamicSharedMemorySize, SMEM1);
    cudaFuncSetAttribute(gemm_kernel<64, 1>,
                         cudaFuncAttributeMaxDynamicSharedMemorySize, SMEM2);

    // graph preprocessing (recomputed every launch: deterministic)
    zero_deg_kernel <<<(RN + 255) / 256, 256>>>();
    count_deg_kernel<<<(RE + 255) / 256, 256>>>(src, dst);
    norm_kernel     <<<(RN + 255) / 256, 256>>>();
    scan_kernel     <<<1, 1024>>>();
    fill_csr_kernel <<<(RE + 255) / 256, 256>>>(src, dst);

    // layer 1: transform-first, then CSR gather + relu
    gemm_kernel<128, 0><<<dim3((NN + 127) / 128, RR), 256, SMEM1>>>(x, W1);
    agg1_kernel<<<(NN * 32 + 255) / 256, 256>>>(b1);

    // layer 2: transform-first (64-wide), then CSR gather -> output
    gemm_kernel<64, 1><<<dim3((NN + 127) / 128, RR), 256, SMEM2>>>(nullptr, W2);
    agg2_kernel<<<(NN * 32 + 255) / 256, 256>>>(b2, out);
}

// round 7
// speedup vs baseline: 1.6686x; 1.6686x over previous
#include <cuda_runtime.h>

#define RR   3
#define NN   50000
#define EE   200000
#define RN   (RR*NN)
#define RE   (RR*EE)
#define DIN  128
#define DHID 128
#define DOUT 64
#define NB   ((RN + 1023) / 1024)   // 147 scan blocks

// ---------------- scratch (device globals; no allocation allowed) ----------
__device__ int   g_deg_out[RN];
__device__ int   g_deg_in [RN];
__device__ float g_onorm  [RN];
__device__ float g_inorm  [RN];
__device__ int   g_rowptr [RN + 1];
__device__ int   g_pos    [RN];
__device__ int   g_colsrc [RE];
__device__ int   g_blocksum[NB];
__device__ int   g_blockoff[NB + 1];
__device__ float g_Y1[(size_t)RN * DHID];   // per-relation transformed feats, layer 1
__device__ float g_H [(size_t)NN * DHID];   // hidden after relu
__device__ float g_Y2[(size_t)RN * DOUT];   // per-relation transformed feats, layer 2

// ---------------- helpers ---------------------------------------------------
__device__ __forceinline__ unsigned long long bcast2(float a) {
    unsigned long long r;
    asm("mov.b64 %0, {%1, %1};" : "=l"(r) : "r"(__float_as_uint(a)));
    return r;
}
__device__ __forceinline__ void fma2(unsigned long long& d,
                                     unsigned long long a,
                                     unsigned long long b) {
    asm("fma.rn.f32x2 %0, %1, %2, %3;" : "=l"(d) : "l"(a), "l"(b), "l"(d));
}

// ---------------- graph preprocessing ---------------------------------------
__global__ void zero_deg_kernel() {
    int i = blockIdx.x * blockDim.x + threadIdx.x;
    if (i < RN) { g_deg_out[i] = 0; g_deg_in[i] = 0; }
}

// 2D grid: y = relation (no integer division per edge)
__global__ void count_deg_kernel(const int* __restrict__ src,
                                 const int* __restrict__ dst) {
    int e = blockIdx.x * blockDim.x + threadIdx.x;
    if (e >= EE) return;
    int r = blockIdx.y;
    int i = r * EE + e;
    atomicAdd(&g_deg_out[r * NN + src[i]], 1);
    atomicAdd(&g_deg_in [r * NN + dst[i]], 1);
}

__global__ void norm_kernel() {
    int i = blockIdx.x * blockDim.x + threadIdx.x;
    if (i >= RN) return;
    int od = g_deg_out[i]; if (od < 1) od = 1;
    int id = g_deg_in [i]; if (id < 1) id = 1;
    g_onorm[i] = rsqrtf((float)od);
    g_inorm[i] = rsqrtf((float)id);
}

// ---- device-wide exclusive scan of g_deg_in, 3 passes ----------------------
// pass 1: per-block inclusive scan (1024 elems/block) + block sums
__global__ void scan1_kernel() {
    __shared__ int sm[1024];
    const int t = threadIdx.x;
    const int i = blockIdx.x * 1024 + t;
    int v = (i < RN) ? g_deg_in[i] : 0;
    sm[t] = v;
    __syncthreads();
    #pragma unroll
    for (int off = 1; off < 1024; off <<= 1) {
        int u = (t >= off) ? sm[t - off] : 0;
        __syncthreads();
        sm[t] += u;
        __syncthreads();
    }
    if (i < RN) g_rowptr[i] = sm[t];          // inclusive, fixed up in pass 3
    if (t == 1023) g_blocksum[blockIdx.x] = sm[1023];
}

// pass 2: scan the NB block sums (single small block)
__global__ void scan2_kernel() {
    __shared__ int sm[256];
    const int t = threadIdx.x;
    int v = (t < NB) ? g_blocksum[t] : 0;
    sm[t] = v;
    __syncthreads();
    #pragma unroll
    for (int off = 1; off < 256; off <<= 1) {
        int u = (t >= off) ? sm[t - off] : 0;
        __syncthreads();
        sm[t] += u;
        __syncthreads();
    }
    if (t < NB) g_blockoff[t] = sm[t] - v;    // exclusive block offsets
    if (t == NB - 1) g_blockoff[NB] = sm[t];  // grand total
}

// pass 3: fixup to exclusive global scan -> rowptr / pos
__global__ void scan3_kernel() {
    int i = blockIdx.x * blockDim.x + threadIdx.x;
    if (i == 0) g_rowptr[RN] = g_blockoff[NB];
    if (i >= RN) return;
    int excl = g_rowptr[i] - g_deg_in[i] + g_blockoff[i >> 10];
    g_rowptr[i] = excl;
    g_pos[i]    = excl;
}

__global__ void fill_csr_kernel(const int* __restrict__ src,
                                const int* __restrict__ dst) {
    int e = blockIdx.x * blockDim.x + threadIdx.x;
    if (e >= EE) return;
    int r = blockIdx.y;
    int i = r * EE + e;
    int p = atomicAdd(&g_pos[r * NN + dst[i]], 1);
    g_colsrc[p] = src[i];
}

// ---------------- batched GEMM:  Y[r] = (onorm_r ⊙ A) @ W[r]  ----------------
// Block tile: 128 rows x BN cols, full K=128 resident in SMEM. 256 threads,
// each computing an 8 x (BN/16) register tile with packed f32x2 FMAs.
template <int BN, int LAYER>
__global__ void __launch_bounds__(256, 1)
gemm_kernel(const float* __restrict__ xin, const float* __restrict__ W) {
    extern __shared__ float sm[];
    float* As = sm;                 // [128][132]  (K-major, padded)
    float* Ws = sm + 128 * 132;     // [128][BN]

    const float* A    = (LAYER == 0) ? xin : g_H;
    float*       Yout = (LAYER == 0) ? g_Y1 : g_Y2;

    const int r    = blockIdx.y;
    const int row0 = blockIdx.x * 128;
    const int t    = threadIdx.x;

    // --- load W[r] (K x BN) straight into SMEM, float4 ---
    const float4* Wr = (const float4*)(W + (size_t)r * 128 * BN);
    #pragma unroll
    for (int i = t; i < 128 * BN / 4; i += 256) ((float4*)Ws)[i] = Wr[i];

    // --- load A tile transposed & scaled by out-norm ---
    for (int i = t; i < 128 * 32; i += 256) {
        int row = i >> 5;           // 0..127
        int k4  = i & 31;           // float4 index along K
        int grow = row0 + row;
        float4 v = make_float4(0.f, 0.f, 0.f, 0.f);
        float  s = 0.f;
        if (grow < NN) {
            v = ((const float4*)(A + (size_t)grow * 128))[k4];
            s = g_onorm[r * NN + grow];
        }
        int kb = k4 * 4;
        As[(kb + 0) * 132 + row] = v.x * s;
        As[(kb + 1) * 132 + row] = v.y * s;
        As[(kb + 2) * 132 + row] = v.z * s;
        As[(kb + 3) * 132 + row] = v.w * s;
    }
    __syncthreads();

    const int tx = t & 15;          // 16 col-groups
    const int ty = t >> 4;          // 16 row-groups
    constexpr int TN = BN / 16;     // 8 (L1) or 4 (L2) cols per thread
    constexpr int NP = TN / 2;      // f32x2 pairs

    unsigned long long acc[8][NP];
    #pragma unroll
    for (int i = 0; i < 8; i++)
        #pragma unroll
        for (int j = 0; j < NP; j++) acc[i][j] = 0ull;

    for (int k = 0; k < 128; k++) {
        const float* ak = &As[k * 132 + ty * 8];
        float4 a0 = *(const float4*)(ak);
        float4 a1 = *(const float4*)(ak + 4);
        unsigned long long aa[8];
        aa[0] = bcast2(a0.x); aa[1] = bcast2(a0.y);
        aa[2] = bcast2(a0.z); aa[3] = bcast2(a0.w);
        aa[4] = bcast2(a1.x); aa[5] = bcast2(a1.y);
        aa[6] = bcast2(a1.z); aa[7] = bcast2(a1.w);

        const ulonglong2* bk = (const ulonglong2*)&Ws[k * BN + tx * TN];
        unsigned long long bb[NP];
        #pragma unroll
        for (int j = 0; j < NP; j += 2) {
            ulonglong2 v = bk[j >> 1];
            bb[j] = v.x;
            bb[j + 1] = v.y;
        }
        #pragma unroll
        for (int i = 0; i < 8; i++)
            #pragma unroll
            for (int j = 0; j < NP; j++) fma2(acc[i][j], aa[i], bb[j]);
    }

    #pragma unroll
    for (int i = 0; i < 8; i++) {
        int grow = row0 + ty * 8 + i;
        if (grow < NN) {
            unsigned long long* dstp =
                (unsigned long long*)&Yout[((size_t)r * NN + grow) * BN + tx * TN];
            #pragma unroll
            for (int j = 0; j < NP; j++) dstp[j] = acc[i][j];
        }
    }
}

// ---------------- aggregation (gather via CSR), layer 1: relu + bias --------
__global__ void agg1_kernel(const float* __restrict__ b1) {
    int gt   = blockIdx.x * blockDim.x + threadIdx.x;
    int n    = gt >> 5;
    int lane = gt & 31;
    if (n >= NN) return;

    float4 acc = make_float4(0.f, 0.f, 0.f, 0.f);
    #pragma unroll
    for (int r = 0; r < RR; r++) {
        int key = r * NN + n;
        int beg = g_rowptr[key];
        int end = g_rowptr[key + 1];
        float4 s = make_float4(0.f, 0.f, 0.f, 0.f);
        for (int j = beg; j < end; j++) {
            int sn = g_colsrc[j];
            float4 v = *(const float4*)&g_Y1[((size_t)r * NN + sn) * DHID + lane * 4];
            s.x += v.x; s.y += v.y; s.z += v.z; s.w += v.w;
        }
        float inn = g_inorm[key];
        acc.x += inn * s.x; acc.y += inn * s.y;
        acc.z += inn * s.z; acc.w += inn * s.w;
    }
    int col = lane * 4;
    acc.x += b1[col + 0] + b1[DHID + col + 0] + b1[2 * DHID + col + 0];
    acc.y += b1[col + 1] + b1[DHID + col + 1] + b1[2 * DHID + col + 1];
    acc.z += b1[col + 2] + b1[DHID + col + 2] + b1[2 * DHID + col + 2];
    acc.w += b1[col + 3] + b1[DHID + col + 3] + b1[2 * DHID + col + 3];
    acc.x = fmaxf(acc.x, 0.f); acc.y = fmaxf(acc.y, 0.f);
    acc.z = fmaxf(acc.z, 0.f); acc.w = fmaxf(acc.w, 0.f);
    *(float4*)&g_H[(size_t)n * DHID + col] = acc;
}

// ---------------- aggregation layer 2: bias, write output -------------------
__global__ void agg2_kernel(const float* __restrict__ b2,
                            float* __restrict__ out) {
    int gt   = blockIdx.x * blockDim.x + threadIdx.x;
    int n    = gt >> 5;
    int lane = gt & 31;
    if (n >= NN) return;

    float2 acc = make_float2(0.f, 0.f);
    #pragma unroll
    for (int r = 0; r < RR; r++) {
        int key = r * NN + n;
        int beg = g_rowptr[key];
        int end = g_rowptr[key + 1];
        float2 s = make_float2(0.f, 0.f);
        for (int j = beg; j < end; j++) {
            int sn = g_colsrc[j];
            float2 v = *(const float2*)&g_Y2[((size_t)r * NN + sn) * DOUT + lane * 2];
            s.x += v.x; s.y += v.y;
        }
        float inn = g_inorm[key];
        acc.x += inn * s.x; acc.y += inn * s.y;
    }
    int col = lane * 2;
    acc.x += b2[col + 0] + b2[DOUT + col + 0] + b2[2 * DOUT + col + 0];
    acc.y += b2[col + 1] + b2[DOUT + col + 1] + b2[2 * DOUT + col + 1];
    *(float2*)&out[(size_t)n * DOUT + col] = acc;
}

// ---------------- launch -----------------------------------------------------
extern "C" void kernel_launch(void* const* d_in, const int* in_sizes, int n_in,
                              void* d_out, int out_size) {
    const float* x   = (const float*)d_in[0];
    const float* W1  = (const float*)d_in[1];
    const float* b1  = (const float*)d_in[2];
    const float* W2  = (const float*)d_in[3];
    const float* b2  = (const float*)d_in[4];
    const int*   src = (const int*)d_in[5];
    const int*   dst = (const int*)d_in[6];
    float*       out = (float*)d_out;

    const int SMEM1 = (128 * 132 + 128 * 128) * 4;   // 133120
    const int SMEM2 = (128 * 132 + 128 * 64) * 4;    // 100352
    cudaFuncSetAttribute(gemm_kernel<128, 0>,
                         cudaFuncAttributeMaxDynamicSharedMemorySize, SMEM1);
    cudaFuncSetAttribute(gemm_kernel<64, 1>,
                         cudaFuncAttributeMaxDynamicSharedMemorySize, SMEM2);

    // graph preprocessing (recomputed every launch: deterministic)
    zero_deg_kernel <<<(RN + 255) / 256, 256>>>();
    count_deg_kernel<<<dim3((EE + 255) / 256, RR), 256>>>(src, dst);
    norm_kernel     <<<(RN + 255) / 256, 256>>>();
    scan1_kernel    <<<NB, 1024>>>();
    scan2_kernel    <<<1, 256>>>();
    scan3_kernel    <<<(RN + 255) / 256, 256>>>();
    fill_csr_kernel <<<dim3((EE + 255) / 256, RR), 256>>>(src, dst);

    // layer 1: transform-first, then CSR gather + relu
    gemm_kernel<128, 0><<<dim3((NN + 127) / 128, RR), 256, SMEM1>>>(x, W1);
    agg1_kernel<<<(NN * 32 + 255) / 256, 256>>>(b1);

    // layer 2: transform-first (64-wide), then CSR gather -> output
    gemm_kernel<64, 1><<<dim3((NN + 127) / 128, RR), 256, SMEM2>>>(nullptr, W2);
    agg2_kernel<<<(NN * 32 + 255) / 256, 256>>>(b2, out);
}

// round 11
// speedup vs baseline: 3.0919x; 1.8530x over previous
#include <cuda_runtime.h>
#include <cuda_bf16.h>
#include <cstdint>

#define RR   3
#define NN   50000
#define EE   200000
#define RN   (RR*NN)
#define RE   (RR*EE)
#define DIN  128
#define DHID 128
#define DOUT 64
#define NB   ((RN + 1023) / 1024)   // 147 scan blocks

// ---------------- scratch (device globals; no allocation allowed) ----------
__device__ int   g_deg_out[RN];
__device__ int   g_deg_in [RN];
__device__ float g_onorm  [RN];
__device__ float g_inorm  [RN];
__device__ int   g_rowptr [RN + 1];
__device__ int   g_pos    [RN];
__device__ int   g_colsrc [RE];
__device__ int   g_blocksum[NB];
__device__ int   g_blockoff[NB + 1];
__device__ float g_Y1[(size_t)RN * DHID];   // per-relation transformed feats, layer 1
__device__ float g_H [(size_t)NN * DHID];   // hidden after relu
__device__ float g_Y2[(size_t)RN * DOUT];   // per-relation transformed feats, layer 2
__device__ __nv_bfloat16 g_W1T_hi[RR * DHID * DIN]; // W1^T [r][n][k], bf16 hi/lo
__device__ __nv_bfloat16 g_W1T_lo[RR * DHID * DIN];
__device__ __nv_bfloat16 g_W2T_hi[RR * DOUT * DHID];
__device__ __nv_bfloat16 g_W2T_lo[RR * DOUT * DHID];

// ---------------- ptx helpers ------------------------------------------------
__device__ __forceinline__ uint32_t smem_u32(const void* p) {
    uint32_t a;
    asm("{ .reg .u64 t; cvta.to.shared.u64 t, %1; cvt.u32.u64 %0, t; }"
        : "=r"(a) : "l"(p));
    return a;
}
__device__ __forceinline__ void ldsm_x4(uint32_t& r0, uint32_t& r1,
                                        uint32_t& r2, uint32_t& r3, uint32_t a) {
    asm volatile("ldmatrix.sync.aligned.m8n8.x4.shared.b16 {%0,%1,%2,%3}, [%4];"
                 : "=r"(r0), "=r"(r1), "=r"(r2), "=r"(r3) : "r"(a));
}
__device__ __forceinline__ void ldsm_x2(uint32_t& r0, uint32_t& r1, uint32_t a) {
    asm volatile("ldmatrix.sync.aligned.m8n8.x2.shared.b16 {%0,%1}, [%2];"
                 : "=r"(r0), "=r"(r1) : "r"(a));
}
__device__ __forceinline__ void mma_bf16(float* d, const uint32_t* a,
                                         const uint32_t* b) {
    asm volatile(
        "mma.sync.aligned.m16n8k16.row.col.f32.bf16.bf16.f32 "
        "{%0,%1,%2,%3}, {%4,%5,%6,%7}, {%8,%9}, {%0,%1,%2,%3};"
        : "+f"(d[0]), "+f"(d[1]), "+f"(d[2]), "+f"(d[3])
        : "r"(a[0]), "r"(a[1]), "r"(a[2]), "r"(a[3]), "r"(b[0]), "r"(b[1]));
}
__device__ __forceinline__ uint32_t b2u(__nv_bfloat162 v) {
    return *reinterpret_cast<uint32_t*>(&v);
}

// ---------------- graph preprocessing ---------------------------------------
__global__ void zero_deg_kernel() {
    int i = blockIdx.x * blockDim.x + threadIdx.x;
    if (i < RN) { g_deg_out[i] = 0; g_deg_in[i] = 0; }
}

__global__ void count_deg_kernel(const int* __restrict__ src,
                                 const int* __restrict__ dst) {
    int e = blockIdx.x * blockDim.x + threadIdx.x;
    if (e >= EE) return;
    int r = blockIdx.y;
    int i = r * EE + e;
    atomicAdd(&g_deg_out[r * NN + src[i]], 1);
    atomicAdd(&g_deg_in [r * NN + dst[i]], 1);
}

__global__ void norm_kernel() {
    int i = blockIdx.x * blockDim.x + threadIdx.x;
    if (i >= RN) return;
    int od = g_deg_out[i]; if (od < 1) od = 1;
    int id = g_deg_in [i]; if (id < 1) id = 1;
    g_onorm[i] = rsqrtf((float)od);
    g_inorm[i] = rsqrtf((float)id);
}

__global__ void scan1_kernel() {
    __shared__ int sm[1024];
    const int t = threadIdx.x;
    const int i = blockIdx.x * 1024 + t;
    int v = (i < RN) ? g_deg_in[i] : 0;
    sm[t] = v;
    __syncthreads();
    #pragma unroll
    for (int off = 1; off < 1024; off <<= 1) {
        int u = (t >= off) ? sm[t - off] : 0;
        __syncthreads();
        sm[t] += u;
        __syncthreads();
    }
    if (i < RN) g_rowptr[i] = sm[t];
    if (t == 1023) g_blocksum[blockIdx.x] = sm[1023];
}

__global__ void scan2_kernel() {
    __shared__ int sm[256];
    const int t = threadIdx.x;
    int v = (t < NB) ? g_blocksum[t] : 0;
    sm[t] = v;
    __syncthreads();
    #pragma unroll
    for (int off = 1; off < 256; off <<= 1) {
        int u = (t >= off) ? sm[t - off] : 0;
        __syncthreads();
        sm[t] += u;
        __syncthreads();
    }
    if (t < NB) g_blockoff[t] = sm[t] - v;
    if (t == NB - 1) g_blockoff[NB] = sm[t];
}

__global__ void scan3_kernel() {
    int i = blockIdx.x * blockDim.x + threadIdx.x;
    if (i == 0) g_rowptr[RN] = g_blockoff[NB];
    if (i >= RN) return;
    int excl = g_rowptr[i] - g_deg_in[i] + g_blockoff[i >> 10];
    g_rowptr[i] = excl;
    g_pos[i]    = excl;
}

__global__ void fill_csr_kernel(const int* __restrict__ src,
                                const int* __restrict__ dst) {
    int e = blockIdx.x * blockDim.x + threadIdx.x;
    if (e >= EE) return;
    int r = blockIdx.y;
    int i = r * EE + e;
    int p = atomicAdd(&g_pos[r * NN + dst[i]], 1);
    g_colsrc[p] = src[i];
}

// transpose + bf16-split W: [r][K=128][Ndim] fp32 -> [r][Ndim][128] bf16 hi/lo
template <int Ndim>
__global__ void wsplit_kernel(const float* __restrict__ W,
                              __nv_bfloat16* __restrict__ Thi,
                              __nv_bfloat16* __restrict__ Tlo) {
    int r = blockIdx.y;
    int i = blockIdx.x * 256 + threadIdx.x;
    if (i >= 128 * Ndim) return;
    int k = i / Ndim, n = i % Ndim;
    float v = W[((size_t)r * 128 + k) * Ndim + n];
    __nv_bfloat16 hi = __float2bfloat16_rn(v);
    __nv_bfloat16 lo = __float2bfloat16_rn(v - __bfloat162float(hi));
    Thi[((size_t)r * Ndim + n) * 128 + k] = hi;
    Tlo[((size_t)r * Ndim + n) * 128 + k] = lo;
}

// ---------------- HMMA bf16x2 3-term GEMM: Y[r] = A @ W[r] ------------------
// A fp32 [NN,128] split hi/lo on the fly into swizzled SMEM (row-major, 256B
// rows, granule g^(row&7)). W^T bf16 hi/lo copied into same layout. Full K
// resident; 8 k-steps of ldmatrix + mma.sync m16n8k16.
template <int N, int LAYER>
__global__ void __launch_bounds__(256)
mma_gemm_kernel(const float* __restrict__ xin) {
    extern __shared__ char smem[];
    const float* A = (LAYER == 0) ? xin : g_H;
    const __nv_bfloat16* Whi = (LAYER == 0) ? g_W1T_hi : g_W2T_hi;
    const __nv_bfloat16* Wlo = (LAYER == 0) ? g_W1T_lo : g_W2T_lo;
    float* Y = (LAYER == 0) ? g_Y1 : g_Y2;

    constexpr int A_BYTES = 128 * 256;
    constexpr int B_BYTES = N * 256;
    constexpr int OFF_AHI = 0;
    constexpr int OFF_ALO = A_BYTES;
    constexpr int OFF_BHI = 2 * A_BYTES;
    constexpr int OFF_BLO = 2 * A_BYTES + B_BYTES;

    const int t = threadIdx.x;
    const int r = blockIdx.y;
    const int row0 = blockIdx.x * 128;

    // ---- B: copy bf16 hi/lo granules into swizzled SMEM ----
    {
        const uint4* bh = (const uint4*)(Whi + (size_t)r * N * 128);
        const uint4* bl = (const uint4*)(Wlo + (size_t)r * N * 128);
        #pragma unroll
        for (int i = t; i < N * 16; i += 256) {
            int n = i >> 4, g = i & 15;
            uint32_t off = n * 256 + ((g ^ (n & 7)) << 4);
            *(uint4*)(smem + OFF_BHI + off) = bh[i];
            *(uint4*)(smem + OFF_BLO + off) = bl[i];
        }
    }
    // ---- A: load fp32, split to bf16 hi/lo, swizzled store ----
    #pragma unroll
    for (int i = t; i < 128 * 16; i += 256) {
        int m = i >> 4, g = i & 15;
        int grow = row0 + m;
        float4 v0 = make_float4(0.f, 0.f, 0.f, 0.f);
        float4 v1 = make_float4(0.f, 0.f, 0.f, 0.f);
        if (grow < NN) {
            const float4* ap = (const float4*)(A + (size_t)grow * 128 + g * 8);
            v0 = ap[0]; v1 = ap[1];
        }
        __nv_bfloat162 h0 = __floats2bfloat162_rn(v0.x, v0.y);
        __nv_bfloat162 h1 = __floats2bfloat162_rn(v0.z, v0.w);
        __nv_bfloat162 h2 = __floats2bfloat162_rn(v1.x, v1.y);
        __nv_bfloat162 h3 = __floats2bfloat162_rn(v1.z, v1.w);
        __nv_bfloat162 l0 = __floats2bfloat162_rn(v0.x - __bfloat162float(h0.x),
                                                  v0.y - __bfloat162float(h0.y));
        __nv_bfloat162 l1 = __floats2bfloat162_rn(v0.z - __bfloat162float(h1.x),
                                                  v0.w - __bfloat162float(h1.y));
        __nv_bfloat162 l2 = __floats2bfloat162_rn(v1.x - __bfloat162float(h2.x),
                                                  v1.y - __bfloat162float(h2.y));
        __nv_bfloat162 l3 = __floats2bfloat162_rn(v1.z - __bfloat162float(h3.x),
                                                  v1.w - __bfloat162float(h3.y));
        uint32_t off = m * 256 + ((g ^ (m & 7)) << 4);
        *(uint4*)(smem + OFF_AHI + off) = make_uint4(b2u(h0), b2u(h1), b2u(h2), b2u(h3));
        *(uint4*)(smem + OFF_ALO + off) = make_uint4(b2u(l0), b2u(l1), b2u(l2), b2u(l3));
    }
    __syncthreads();

    // ---- warp tiling ----
    constexpr int WM = (N == 128) ? 64 : 32;    // warp M tile
    constexpr int WN = 32;                      // warp N tile
    constexpr int WX = N / WN;                  // warps along N
    constexpr int MI = WM / 16, NI = WN / 8;
    const int wid = t >> 5, lane = t & 31;
    const int wm0 = (wid / WX) * WM;
    const int wn0 = (wid % WX) * WN;

    float acc[MI][NI][4];
    #pragma unroll
    for (int mi = 0; mi < MI; mi++)
        #pragma unroll
        for (int ni = 0; ni < NI; ni++)
            #pragma unroll
            for (int q = 0; q < 4; q++) acc[mi][ni][q] = 0.f;

    const uint32_t sbase = smem_u32(smem);
    const int a_row = (lane & 15);
    const int a_kg  = (lane >> 4);              // 0/1
    const int b_n   = (lane & 7);
    const int b_kg  = ((lane >> 3) & 1);

    #pragma unroll
    for (int ks = 0; ks < 8; ks++) {
        uint32_t ah[MI][4], al[MI][4];
        #pragma unroll
        for (int mi = 0; mi < MI; mi++) {
            int row = wm0 + mi * 16 + a_row;
            int kg  = ks * 2 + a_kg;
            uint32_t off = row * 256 + ((kg ^ (row & 7)) << 4);
            ldsm_x4(ah[mi][0], ah[mi][1], ah[mi][2], ah[mi][3],
                    sbase + OFF_AHI + off);
            ldsm_x4(al[mi][0], al[mi][1], al[mi][2], al[mi][3],
                    sbase + OFF_ALO + off);
        }
        uint32_t bh[NI][2], bl[NI][2];
        #pragma unroll
        for (int ni = 0; ni < NI; ni++) {
            int n  = wn0 + ni * 8 + b_n;
            int kg = ks * 2 + b_kg;
            uint32_t off = n * 256 + ((kg ^ (n & 7)) << 4);
            ldsm_x2(bh[ni][0], bh[ni][1], sbase + OFF_BHI + off);
            ldsm_x2(bl[ni][0], bl[ni][1], sbase + OFF_BLO + off);
        }
        #pragma unroll
        for (int mi = 0; mi < MI; mi++)
            #pragma unroll
            for (int ni = 0; ni < NI; ni++) {
                mma_bf16(acc[mi][ni], ah[mi], bh[ni]);  // hi*hi
                mma_bf16(acc[mi][ni], ah[mi], bl[ni]);  // hi*lo
                mma_bf16(acc[mi][ni], al[mi], bh[ni]);  // lo*hi
            }
    }

    // ---- epilogue: write fp32 Y ----
    #pragma unroll
    for (int mi = 0; mi < MI; mi++) {
        int m0 = row0 + wm0 + mi * 16 + (lane >> 2);
        #pragma unroll
        for (int ni = 0; ni < NI; ni++) {
            int n = wn0 + ni * 8 + 2 * (lane & 3);
            if (m0 < NN)
                *(float2*)&Y[((size_t)r * NN + m0) * N + n] =
                    make_float2(acc[mi][ni][0], acc[mi][ni][1]);
            if (m0 + 8 < NN)
                *(float2*)&Y[((size_t)r * NN + m0 + 8) * N + n] =
                    make_float2(acc[mi][ni][2], acc[mi][ni][3]);
        }
    }
}

// ---------------- aggregation (gather via CSR), onorm folded per-edge -------
__global__ void agg1_kernel(const float* __restrict__ b1) {
    int gt   = blockIdx.x * blockDim.x + threadIdx.x;
    int n    = gt >> 5;
    int lane = gt & 31;
    if (n >= NN) return;

    float4 acc = make_float4(0.f, 0.f, 0.f, 0.f);
    #pragma unroll
    for (int r = 0; r < RR; r++) {
        int key = r * NN + n;
        int beg = g_rowptr[key];
        int end = g_rowptr[key + 1];
        float4 s = make_float4(0.f, 0.f, 0.f, 0.f);
        for (int j = beg; j < end; j++) {
            int sn = g_colsrc[j];
            float on = g_onorm[r * NN + sn];
            float4 v = *(const float4*)&g_Y1[((size_t)r * NN + sn) * DHID + lane * 4];
            s.x += on * v.x; s.y += on * v.y; s.z += on * v.z; s.w += on * v.w;
        }
        float inn = g_inorm[key];
        acc.x += inn * s.x; acc.y += inn * s.y;
        acc.z += inn * s.z; acc.w += inn * s.w;
    }
    int col = lane * 4;
    acc.x += b1[col + 0] + b1[DHID + col + 0] + b1[2 * DHID + col + 0];
    acc.y += b1[col + 1] + b1[DHID + col + 1] + b1[2 * DHID + col + 1];
    acc.z += b1[col + 2] + b1[DHID + col + 2] + b1[2 * DHID + col + 2];
    acc.w += b1[col + 3] + b1[DHID + col + 3] + b1[2 * DHID + col + 3];
    acc.x = fmaxf(acc.x, 0.f); acc.y = fmaxf(acc.y, 0.f);
    acc.z = fmaxf(acc.z, 0.f); acc.w = fmaxf(acc.w, 0.f);
    *(float4*)&g_H[(size_t)n * DHID + col] = acc;
}

__global__ void agg2_kernel(const float* __restrict__ b2,
                            float* __restrict__ out) {
    int gt   = blockIdx.x * blockDim.x + threadIdx.x;
    int n    = gt >> 5;
    int lane = gt & 31;
    if (n >= NN) return;

    float2 acc = make_float2(0.f, 0.f);
    #pragma unroll
    for (int r = 0; r < RR; r++) {
        int key = r * NN + n;
        int beg = g_rowptr[key];
        int end = g_rowptr[key + 1];
        float2 s = make_float2(0.f, 0.f);
        for (int j = beg; j < end; j++) {
            int sn = g_colsrc[j];
            float on = g_onorm[r * NN + sn];
            float2 v = *(const float2*)&g_Y2[((size_t)r * NN + sn) * DOUT + lane * 2];
            s.x += on * v.x; s.y += on * v.y;
        }
        float inn = g_inorm[key];
        acc.x += inn * s.x; acc.y += inn * s.y;
    }
    int col = lane * 2;
    acc.x += b2[col + 0] + b2[DOUT + col + 0] + b2[2 * DOUT + col + 0];
    acc.y += b2[col + 1] + b2[DOUT + col + 1] + b2[2 * DOUT + col + 1];
    *(float2*)&out[(size_t)n * DOUT + col] = acc;
}

// ---------------- launch -----------------------------------------------------
extern "C" void kernel_launch(void* const* d_in, const int* in_sizes, int n_in,
                              void* d_out, int out_size) {
    const float* x   = (const float*)d_in[0];
    const float* W1  = (const float*)d_in[1];
    const float* b1  = (const float*)d_in[2];
    const float* W2  = (const float*)d_in[3];
    const float* b2  = (const float*)d_in[4];
    const int*   src = (const int*)d_in[5];
    const int*   dst = (const int*)d_in[6];
    float*       out = (float*)d_out;

    __nv_bfloat16 *w1hi, *w1lo, *w2hi, *w2lo;
    cudaGetSymbolAddress((void**)&w1hi, g_W1T_hi);
    cudaGetSymbolAddress((void**)&w1lo, g_W1T_lo);
    cudaGetSymbolAddress((void**)&w2hi, g_W2T_hi);
    cudaGetSymbolAddress((void**)&w2lo, g_W2T_lo);

    const int SMEM1 = 2 * (128 * 256) + 2 * (128 * 256);  // 131072
    const int SMEM2 = 2 * (128 * 256) + 2 * ( 64 * 256);  //  98304
    cudaFuncSetAttribute(mma_gemm_kernel<128, 0>,
                         cudaFuncAttributeMaxDynamicSharedMemorySize, SMEM1);
    cudaFuncSetAttribute(mma_gemm_kernel<64, 1>,
                         cudaFuncAttributeMaxDynamicSharedMemorySize, SMEM2);

    // graph preprocessing (recomputed every launch: deterministic)
    zero_deg_kernel <<<(RN + 255) / 256, 256>>>();
    count_deg_kernel<<<dim3((EE + 255) / 256, RR), 256>>>(src, dst);
    norm_kernel     <<<(RN + 255) / 256, 256>>>();
    scan1_kernel    <<<NB, 1024>>>();
    scan2_kernel    <<<1, 256>>>();
    scan3_kernel    <<<(RN + 255) / 256, 256>>>();
    fill_csr_kernel <<<dim3((EE + 255) / 256, RR), 256>>>(src, dst);

    // weight transpose + bf16 hi/lo split (tiny)
    wsplit_kernel<DHID><<<dim3((128 * DHID + 255) / 256, RR), 256>>>(W1, w1hi, w1lo);
    wsplit_kernel<DOUT><<<dim3((128 * DOUT + 255) / 256, RR), 256>>>(W2, w2hi, w2lo);

    // layer 1: tensor-core transform, then CSR gather (+onorm) + relu
    mma_gemm_kernel<128, 0><<<dim3((NN + 127) / 128, RR), 256, SMEM1>>>(x);
    agg1_kernel<<<(NN * 32 + 255) / 256, 256>>>(b1);

    // layer 2
    mma_gemm_kernel<64, 1><<<dim3((NN + 127) / 128, RR), 256, SMEM2>>>(nullptr);
    agg2_kernel<<<(NN * 32 + 255) / 256, 256>>>(b2, out);
}

// round 12
// speedup vs baseline: 3.0925x; 1.0002x over previous
#include <cuda_runtime.h>
#include <cuda_bf16.h>
#include <cstdint>

#define RR   3
#define NN   50000
#define EE   200000
#define RN   (RR*NN)
#define RE   (RR*EE)
#define DIN  128
#define DHID 128
#define DOUT 64
#define NB   ((RN + 1023) / 1024)   // 147 scan blocks

// ---------------- scratch (device globals; no allocation allowed) ----------
__device__ int   g_deg_out[RN];
__device__ int   g_deg_in [RN];
__device__ float g_onorm  [RN];
__device__ float g_inorm  [RN];
__device__ int   g_rowptr [RN + 1];
__device__ int   g_pos    [RN];
__device__ int   g_colsrc [RE];
__device__ int   g_blocksum[NB];
__device__ int   g_blockoff[NB + 1];
__device__ float g_Y1[(size_t)RN * DHID];   // per-relation transformed feats, layer 1
__device__ float g_H [(size_t)NN * DHID];   // hidden after relu
__device__ float g_Y2[(size_t)RN * DOUT];   // per-relation transformed feats, layer 2
__device__ __nv_bfloat16 g_W1T_hi[RR * DHID * DIN]; // W1^T [r][n][k], bf16 hi/lo
__device__ __nv_bfloat16 g_W1T_lo[RR * DHID * DIN];
__device__ __nv_bfloat16 g_W2T_hi[RR * DOUT * DHID];
__device__ __nv_bfloat16 g_W2T_lo[RR * DOUT * DHID];

// ---------------- ptx helpers ------------------------------------------------
__device__ __forceinline__ uint32_t smem_u32(const void* p) {
    uint32_t a;
    asm("{ .reg .u64 t; cvta.to.shared.u64 t, %1; cvt.u32.u64 %0, t; }"
        : "=r"(a) : "l"(p));
    return a;
}
__device__ __forceinline__ void ldsm_x4(uint32_t& r0, uint32_t& r1,
                                        uint32_t& r2, uint32_t& r3, uint32_t a) {
    asm volatile("ldmatrix.sync.aligned.m8n8.x4.shared.b16 {%0,%1,%2,%3}, [%4];"
                 : "=r"(r0), "=r"(r1), "=r"(r2), "=r"(r3) : "r"(a));
}
__device__ __forceinline__ void ldsm_x2(uint32_t& r0, uint32_t& r1, uint32_t a) {
    asm volatile("ldmatrix.sync.aligned.m8n8.x2.shared.b16 {%0,%1}, [%2];"
                 : "=r"(r0), "=r"(r1) : "r"(a));
}
__device__ __forceinline__ void mma_bf16(float* d, const uint32_t* a,
                                         const uint32_t* b) {
    asm volatile(
        "mma.sync.aligned.m16n8k16.row.col.f32.bf16.bf16.f32 "
        "{%0,%1,%2,%3}, {%4,%5,%6,%7}, {%8,%9}, {%0,%1,%2,%3};"
        : "+f"(d[0]), "+f"(d[1]), "+f"(d[2]), "+f"(d[3])
        : "r"(a[0]), "r"(a[1]), "r"(a[2]), "r"(a[3]), "r"(b[0]), "r"(b[1]));
}
__device__ __forceinline__ uint32_t b2u(__nv_bfloat162 v) {
    return *reinterpret_cast<uint32_t*>(&v);
}

// ---------------- graph preprocessing ---------------------------------------
__global__ void zero_deg_kernel() {
    int i = blockIdx.x * blockDim.x + threadIdx.x;
    if (i < RN) { g_deg_out[i] = 0; g_deg_in[i] = 0; }
}

__global__ void count_deg_kernel(const int* __restrict__ src,
                                 const int* __restrict__ dst) {
    int e = blockIdx.x * blockDim.x + threadIdx.x;
    if (e >= EE) return;
    int r = blockIdx.y;
    int i = r * EE + e;
    atomicAdd(&g_deg_out[r * NN + src[i]], 1);
    atomicAdd(&g_deg_in [r * NN + dst[i]], 1);
}

__global__ void norm_kernel() {
    int i = blockIdx.x * blockDim.x + threadIdx.x;
    if (i >= RN) return;
    int od = g_deg_out[i]; if (od < 1) od = 1;
    int id = g_deg_in [i]; if (id < 1) id = 1;
    g_onorm[i] = rsqrtf((float)od);
    g_inorm[i] = rsqrtf((float)id);
}

__global__ void scan1_kernel() {
    __shared__ int sm[1024];
    const int t = threadIdx.x;
    const int i = blockIdx.x * 1024 + t;
    int v = (i < RN) ? g_deg_in[i] : 0;
    sm[t] = v;
    __syncthreads();
    #pragma unroll
    for (int off = 1; off < 1024; off <<= 1) {
        int u = (t >= off) ? sm[t - off] : 0;
        __syncthreads();
        sm[t] += u;
        __syncthreads();
    }
    if (i < RN) g_rowptr[i] = sm[t];
    if (t == 1023) g_blocksum[blockIdx.x] = sm[1023];
}

__global__ void scan2_kernel() {
    __shared__ int sm[256];
    const int t = threadIdx.x;
    int v = (t < NB) ? g_blocksum[t] : 0;
    sm[t] = v;
    __syncthreads();
    #pragma unroll
    for (int off = 1; off < 256; off <<= 1) {
        int u = (t >= off) ? sm[t - off] : 0;
        __syncthreads();
        sm[t] += u;
        __syncthreads();
    }
    if (t < NB) g_blockoff[t] = sm[t] - v;
    if (t == NB - 1) g_blockoff[NB] = sm[t];
}

__global__ void scan3_kernel() {
    int i = blockIdx.x * blockDim.x + threadIdx.x;
    if (i == 0) g_rowptr[RN] = g_blockoff[NB];
    if (i >= RN) return;
    int excl = g_rowptr[i] - g_deg_in[i] + g_blockoff[i >> 10];
    g_rowptr[i] = excl;
    g_pos[i]    = excl;
}

__global__ void fill_csr_kernel(const int* __restrict__ src,
                                const int* __restrict__ dst) {
    int e = blockIdx.x * blockDim.x + threadIdx.x;
    if (e >= EE) return;
    int r = blockIdx.y;
    int i = r * EE + e;
    int p = atomicAdd(&g_pos[r * NN + dst[i]], 1);
    g_colsrc[p] = src[i];
}

// transpose + bf16-split W: [r][K=128][Ndim] fp32 -> [r][Ndim][128] bf16 hi/lo
template <int Ndim>
__global__ void wsplit_kernel(const float* __restrict__ W,
                              __nv_bfloat16* __restrict__ Thi,
                              __nv_bfloat16* __restrict__ Tlo) {
    int r = blockIdx.y;
    int i = blockIdx.x * 256 + threadIdx.x;
    if (i >= 128 * Ndim) return;
    int k = i / Ndim, n = i % Ndim;
    float v = W[((size_t)r * 128 + k) * Ndim + n];
    __nv_bfloat16 hi = __float2bfloat16_rn(v);
    __nv_bfloat16 lo = __float2bfloat16_rn(v - __bfloat162float(hi));
    Thi[((size_t)r * Ndim + n) * 128 + k] = hi;
    Tlo[((size_t)r * Ndim + n) * 128 + k] = lo;
}

// ---------------- HMMA bf16x2 3-term GEMM: Y[r] = A @ W[r] ------------------
// A fp32 [NN,128] split hi/lo on the fly into swizzled SMEM (row-major, 256B
// rows, granule g^(row&7)). W^T bf16 hi/lo copied into same layout. Full K
// resident; 8 k-steps of ldmatrix + mma.sync m16n8k16.
template <int N, int LAYER>
__global__ void __launch_bounds__(256)
mma_gemm_kernel(const float* __restrict__ xin) {
    extern __shared__ char smem[];
    const float* A = (LAYER == 0) ? xin : g_H;
    const __nv_bfloat16* Whi = (LAYER == 0) ? g_W1T_hi : g_W2T_hi;
    const __nv_bfloat16* Wlo = (LAYER == 0) ? g_W1T_lo : g_W2T_lo;
    float* Y = (LAYER == 0) ? g_Y1 : g_Y2;

    constexpr int A_BYTES = 128 * 256;
    constexpr int B_BYTES = N * 256;
    constexpr int OFF_AHI = 0;
    constexpr int OFF_ALO = A_BYTES;
    constexpr int OFF_BHI = 2 * A_BYTES;
    constexpr int OFF_BLO = 2 * A_BYTES + B_BYTES;

    const int t = threadIdx.x;
    const int r = blockIdx.y;
    const int row0 = blockIdx.x * 128;

    // ---- B: copy bf16 hi/lo granules into swizzled SMEM ----
    {
        const uint4* bh = (const uint4*)(Whi + (size_t)r * N * 128);
        const uint4* bl = (const uint4*)(Wlo + (size_t)r * N * 128);
        #pragma unroll
        for (int i = t; i < N * 16; i += 256) {
            int n = i >> 4, g = i & 15;
            uint32_t off = n * 256 + ((g ^ (n & 7)) << 4);
            *(uint4*)(smem + OFF_BHI + off) = bh[i];
            *(uint4*)(smem + OFF_BLO + off) = bl[i];
        }
    }
    // ---- A: load fp32, split to bf16 hi/lo, swizzled store ----
    #pragma unroll
    for (int i = t; i < 128 * 16; i += 256) {
        int m = i >> 4, g = i & 15;
        int grow = row0 + m;
        float4 v0 = make_float4(0.f, 0.f, 0.f, 0.f);
        float4 v1 = make_float4(0.f, 0.f, 0.f, 0.f);
        if (grow < NN) {
            const float4* ap = (const float4*)(A + (size_t)grow * 128 + g * 8);
            v0 = ap[0]; v1 = ap[1];
        }
        __nv_bfloat162 h0 = __floats2bfloat162_rn(v0.x, v0.y);
        __nv_bfloat162 h1 = __floats2bfloat162_rn(v0.z, v0.w);
        __nv_bfloat162 h2 = __floats2bfloat162_rn(v1.x, v1.y);
        __nv_bfloat162 h3 = __floats2bfloat162_rn(v1.z, v1.w);
        __nv_bfloat162 l0 = __floats2bfloat162_rn(v0.x - __bfloat162float(h0.x),
                                                  v0.y - __bfloat162float(h0.y));
        __nv_bfloat162 l1 = __floats2bfloat162_rn(v0.z - __bfloat162float(h1.x),
                                                  v0.w - __bfloat162float(h1.y));
        __nv_bfloat162 l2 = __floats2bfloat162_rn(v1.x - __bfloat162float(h2.x),
                                                  v1.y - __bfloat162float(h2.y));
        __nv_bfloat162 l3 = __floats2bfloat162_rn(v1.z - __bfloat162float(h3.x),
                                                  v1.w - __bfloat162float(h3.y));
        uint32_t off = m * 256 + ((g ^ (m & 7)) << 4);
        *(uint4*)(smem + OFF_AHI + off) = make_uint4(b2u(h0), b2u(h1), b2u(h2), b2u(h3));
        *(uint4*)(smem + OFF_ALO + off) = make_uint4(b2u(l0), b2u(l1), b2u(l2), b2u(l3));
    }
    __syncthreads();

    // ---- warp tiling ----
    constexpr int WM = (N == 128) ? 64 : 32;    // warp M tile
    constexpr int WN = 32;                      // warp N tile
    constexpr int WX = N / WN;                  // warps along N
    constexpr int MI = WM / 16, NI = WN / 8;
    const int wid = t >> 5, lane = t & 31;
    const int wm0 = (wid / WX) * WM;
    const int wn0 = (wid % WX) * WN;

    float acc[MI][NI][4];
    #pragma unroll
    for (int mi = 0; mi < MI; mi++)
        #pragma unroll
        for (int ni = 0; ni < NI; ni++)
            #pragma unroll
            for (int q = 0; q < 4; q++) acc[mi][ni][q] = 0.f;

    const uint32_t sbase = smem_u32(smem);
    const int a_row = (lane & 15);
    const int a_kg  = (lane >> 4);              // 0/1
    const int b_n   = (lane & 7);
    const int b_kg  = ((lane >> 3) & 1);

    #pragma unroll
    for (int ks = 0; ks < 8; ks++) {
        uint32_t ah[MI][4], al[MI][4];
        #pragma unroll
        for (int mi = 0; mi < MI; mi++) {
            int row = wm0 + mi * 16 + a_row;
            int kg  = ks * 2 + a_kg;
            uint32_t off = row * 256 + ((kg ^ (row & 7)) << 4);
            ldsm_x4(ah[mi][0], ah[mi][1], ah[mi][2], ah[mi][3],
                    sbase + OFF_AHI + off);
            ldsm_x4(al[mi][0], al[mi][1], al[mi][2], al[mi][3],
                    sbase + OFF_ALO + off);
        }
        uint32_t bh[NI][2], bl[NI][2];
        #pragma unroll
        for (int ni = 0; ni < NI; ni++) {
            int n  = wn0 + ni * 8 + b_n;
            int kg = ks * 2 + b_kg;
            uint32_t off = n * 256 + ((kg ^ (n & 7)) << 4);
            ldsm_x2(bh[ni][0], bh[ni][1], sbase + OFF_BHI + off);
            ldsm_x2(bl[ni][0], bl[ni][1], sbase + OFF_BLO + off);
        }
        #pragma unroll
        for (int mi = 0; mi < MI; mi++)
            #pragma unroll
            for (int ni = 0; ni < NI; ni++) {
                mma_bf16(acc[mi][ni], ah[mi], bh[ni]);  // hi*hi
                mma_bf16(acc[mi][ni], ah[mi], bl[ni]);  // hi*lo
                mma_bf16(acc[mi][ni], al[mi], bh[ni]);  // lo*hi
            }
    }

    // ---- epilogue: write fp32 Y ----
    #pragma unroll
    for (int mi = 0; mi < MI; mi++) {
        int m0 = row0 + wm0 + mi * 16 + (lane >> 2);
        #pragma unroll
        for (int ni = 0; ni < NI; ni++) {
            int n = wn0 + ni * 8 + 2 * (lane & 3);
            if (m0 < NN)
                *(float2*)&Y[((size_t)r * NN + m0) * N + n] =
                    make_float2(acc[mi][ni][0], acc[mi][ni][1]);
            if (m0 + 8 < NN)
                *(float2*)&Y[((size_t)r * NN + m0 + 8) * N + n] =
                    make_float2(acc[mi][ni][2], acc[mi][ni][3]);
        }
    }
}

// ---------------- aggregation (gather via CSR), onorm folded per-edge -------
__global__ void agg1_kernel(const float* __restrict__ b1) {
    int gt   = blockIdx.x * blockDim.x + threadIdx.x;
    int n    = gt >> 5;
    int lane = gt & 31;
    if (n >= NN) return;

    float4 acc = make_float4(0.f, 0.f, 0.f, 0.f);
    #pragma unroll
    for (int r = 0; r < RR; r++) {
        int key = r * NN + n;
        int beg = g_rowptr[key];
        int end = g_rowptr[key + 1];
        float4 s = make_float4(0.f, 0.f, 0.f, 0.f);
        for (int j = beg; j < end; j++) {
            int sn = g_colsrc[j];
            float on = g_onorm[r * NN + sn];
            float4 v = *(const float4*)&g_Y1[((size_t)r * NN + sn) * DHID + lane * 4];
            s.x += on * v.x; s.y += on * v.y; s.z += on * v.z; s.w += on * v.w;
        }
        float inn = g_inorm[key];
        acc.x += inn * s.x; acc.y += inn * s.y;
        acc.z += inn * s.z; acc.w += inn * s.w;
    }
    int col = lane * 4;
    acc.x += b1[col + 0] + b1[DHID + col + 0] + b1[2 * DHID + col + 0];
    acc.y += b1[col + 1] + b1[DHID + col + 1] + b1[2 * DHID + col + 1];
    acc.z += b1[col + 2] + b1[DHID + col + 2] + b1[2 * DHID + col + 2];
    acc.w += b1[col + 3] + b1[DHID + col + 3] + b1[2 * DHID + col + 3];
    acc.x = fmaxf(acc.x, 0.f); acc.y = fmaxf(acc.y, 0.f);
    acc.z = fmaxf(acc.z, 0.f); acc.w = fmaxf(acc.w, 0.f);
    *(float4*)&g_H[(size_t)n * DHID + col] = acc;
}

__global__ void agg2_kernel(const float* __restrict__ b2,
                            float* __restrict__ out) {
    int gt   = blockIdx.x * blockDim.x + threadIdx.x;
    int n    = gt >> 5;
    int lane = gt & 31;
    if (n >= NN) return;

    float2 acc = make_float2(0.f, 0.f);
    #pragma unroll
    for (int r = 0; r < RR; r++) {
        int key = r * NN + n;
        int beg = g_rowptr[key];
        int end = g_rowptr[key + 1];
        float2 s = make_float2(0.f, 0.f);
        for (int j = beg; j < end; j++) {
            int sn = g_colsrc[j];
            float on = g_onorm[r * NN + sn];
            float2 v = *(const float2*)&g_Y2[((size_t)r * NN + sn) * DOUT + lane * 2];
            s.x += on * v.x; s.y += on * v.y;
        }
        float inn = g_inorm[key];
        acc.x += inn * s.x; acc.y += inn * s.y;
    }
    int col = lane * 2;
    acc.x += b2[col + 0] + b2[DOUT + col + 0] + b2[2 * DOUT + col + 0];
    acc.y += b2[col + 1] + b2[DOUT + col + 1] + b2[2 * DOUT + col + 1];
    *(float2*)&out[(size_t)n * DOUT + col] = acc;
}

// ---------------- launch -----------------------------------------------------
extern "C" void kernel_launch(void* const* d_in, const int* in_sizes, int n_in,
                              void* d_out, int out_size) {
    const float* x   = (const float*)d_in[0];
    const float* W1  = (const float*)d_in[1];
    const float* b1  = (const float*)d_in[2];
    const float* W2  = (const float*)d_in[3];
    const float* b2  = (const float*)d_in[4];
    const int*   src = (const int*)d_in[5];
    const int*   dst = (const int*)d_in[6];
    float*       out = (float*)d_out;

    __nv_bfloat16 *w1hi, *w1lo, *w2hi, *w2lo;
    cudaGetSymbolAddress((void**)&w1hi, g_W1T_hi);
    cudaGetSymbolAddress((void**)&w1lo, g_W1T_lo);
    cudaGetSymbolAddress((void**)&w2hi, g_W2T_hi);
    cudaGetSymbolAddress((void**)&w2lo, g_W2T_lo);

    const int SMEM1 = 2 * (128 * 256) + 2 * (128 * 256);  // 131072
    const int SMEM2 = 2 * (128 * 256) + 2 * ( 64 * 256);  //  98304
    cudaFuncSetAttribute(mma_gemm_kernel<128, 0>,
                         cudaFuncAttributeMaxDynamicSharedMemorySize, SMEM1);
    cudaFuncSetAttribute(mma_gemm_kernel<64, 1>,
                         cudaFuncAttributeMaxDynamicSharedMemorySize, SMEM2);

    // graph preprocessing (recomputed every launch: deterministic)
    zero_deg_kernel <<<(RN + 255) / 256, 256>>>();
    count_deg_kernel<<<dim3((EE + 255) / 256, RR), 256>>>(src, dst);
    norm_kernel     <<<(RN + 255) / 256, 256>>>();
    scan1_kernel    <<<NB, 1024>>>();
    scan2_kernel    <<<1, 256>>>();
    scan3_kernel    <<<(RN + 255) / 256, 256>>>();
    fill_csr_kernel <<<dim3((EE + 255) / 256, RR), 256>>>(src, dst);

    // weight transpose + bf16 hi/lo split (tiny)
    wsplit_kernel<DHID><<<dim3((128 * DHID + 255) / 256, RR), 256>>>(W1, w1hi, w1lo);
    wsplit_kernel<DOUT><<<dim3((128 * DOUT + 255) / 256, RR), 256>>>(W2, w2hi, w2lo);

    // layer 1: tensor-core transform, then CSR gather (+onorm) + relu
    mma_gemm_kernel<128, 0><<<dim3((NN + 127) / 128, RR), 256, SMEM1>>>(x);
    agg1_kernel<<<(NN * 32 + 255) / 256, 256>>>(b1);

    // layer 2
    mma_gemm_kernel<64, 1><<<dim3((NN + 127) / 128, RR), 256, SMEM2>>>(nullptr);
    agg2_kernel<<<(NN * 32 + 255) / 256, 256>>>(b2, out);
}

// round 13
// speedup vs baseline: 3.4357x; 1.1110x over previous
#include <cuda_runtime.h>
#include <cuda_bf16.h>
#include <cuda_fp16.h>
#include <cstdint>

#define RR   3
#define NN   50000
#define EE   200000
#define RN   (RR*NN)
#define RE   (RR*EE)
#define DIN  128
#define DHID 128
#define DOUT 64
#define NB   ((RN + 1023) / 1024)   // 147 scan blocks

// ---------------- scratch (device globals; no allocation allowed) ----------
__device__ int   g_deg_out[RN];
__device__ int   g_deg_in [RN];
__device__ float g_onorm  [RN];
__device__ float g_inorm  [RN];
__device__ int   g_rowptr [RN + 1];
__device__ int   g_pos    [RN];
__device__ int   g_colsrc [RE];
__device__ int   g_blocksum[NB];
__device__ int   g_blockoff[NB + 1];
__device__ __half g_Y1h[(size_t)RN * DHID];  // per-relation transformed feats (fp16)
__device__ float  g_H  [(size_t)NN * DHID];  // hidden after relu (fp32)
__device__ __half g_Y2h[(size_t)RN * DOUT];
__device__ __nv_bfloat16 g_W1T_hi[RR * DHID * DIN]; // W1^T [r][n][k], bf16 hi/lo
__device__ __nv_bfloat16 g_W1T_lo[RR * DHID * DIN];
__device__ __nv_bfloat16 g_W2T_hi[RR * DOUT * DHID];
__device__ __nv_bfloat16 g_W2T_lo[RR * DOUT * DHID];

// ---------------- ptx helpers ------------------------------------------------
__device__ __forceinline__ uint32_t smem_u32(const void* p) {
    uint32_t a;
    asm("{ .reg .u64 t; cvta.to.shared.u64 t, %1; cvt.u32.u64 %0, t; }"
        : "=r"(a) : "l"(p));
    return a;
}
__device__ __forceinline__ void ldsm_x4(uint32_t& r0, uint32_t& r1,
                                        uint32_t& r2, uint32_t& r3, uint32_t a) {
    asm volatile("ldmatrix.sync.aligned.m8n8.x4.shared.b16 {%0,%1,%2,%3}, [%4];"
                 : "=r"(r0), "=r"(r1), "=r"(r2), "=r"(r3) : "r"(a));
}
__device__ __forceinline__ void ldsm_x2(uint32_t& r0, uint32_t& r1, uint32_t a) {
    asm volatile("ldmatrix.sync.aligned.m8n8.x2.shared.b16 {%0,%1}, [%2];"
                 : "=r"(r0), "=r"(r1) : "r"(a));
}
__device__ __forceinline__ void mma_bf16(float* d, const uint32_t* a,
                                         const uint32_t* b) {
    asm volatile(
        "mma.sync.aligned.m16n8k16.row.col.f32.bf16.bf16.f32 "
        "{%0,%1,%2,%3}, {%4,%5,%6,%7}, {%8,%9}, {%0,%1,%2,%3};"
        : "+f"(d[0]), "+f"(d[1]), "+f"(d[2]), "+f"(d[3])
        : "r"(a[0]), "r"(a[1]), "r"(a[2]), "r"(a[3]), "r"(b[0]), "r"(b[1]));
}
__device__ __forceinline__ uint32_t b2u(__nv_bfloat162 v) {
    return *reinterpret_cast<uint32_t*>(&v);
}

// ---------------- graph preprocessing ---------------------------------------
__global__ void zero_deg_kernel() {
    int i = blockIdx.x * blockDim.x + threadIdx.x;
    if (i < RN) { g_deg_out[i] = 0; g_deg_in[i] = 0; }
}

__global__ void count_deg_kernel(const int* __restrict__ src,
                                 const int* __restrict__ dst) {
    int e = blockIdx.x * blockDim.x + threadIdx.x;
    if (e >= EE) return;
    int r = blockIdx.y;
    int i = r * EE + e;
    atomicAdd(&g_deg_out[r * NN + src[i]], 1);
    atomicAdd(&g_deg_in [r * NN + dst[i]], 1);
}

__global__ void norm_kernel() {
    int i = blockIdx.x * blockDim.x + threadIdx.x;
    if (i >= RN) return;
    int od = g_deg_out[i]; if (od < 1) od = 1;
    int id = g_deg_in [i]; if (id < 1) id = 1;
    g_onorm[i] = rsqrtf((float)od);
    g_inorm[i] = rsqrtf((float)id);
}

__global__ void scan1_kernel() {
    __shared__ int sm[1024];
    const int t = threadIdx.x;
    const int i = blockIdx.x * 1024 + t;
    int v = (i < RN) ? g_deg_in[i] : 0;
    sm[t] = v;
    __syncthreads();
    #pragma unroll
    for (int off = 1; off < 1024; off <<= 1) {
        int u = (t >= off) ? sm[t - off] : 0;
        __syncthreads();
        sm[t] += u;
        __syncthreads();
    }
    if (i < RN) g_rowptr[i] = sm[t];
    if (t == 1023) g_blocksum[blockIdx.x] = sm[1023];
}

__global__ void scan2_kernel() {
    __shared__ int sm[256];
    const int t = threadIdx.x;
    int v = (t < NB) ? g_blocksum[t] : 0;
    sm[t] = v;
    __syncthreads();
    #pragma unroll
    for (int off = 1; off < 256; off <<= 1) {
        int u = (t >= off) ? sm[t - off] : 0;
        __syncthreads();
        sm[t] += u;
        __syncthreads();
    }
    if (t < NB) g_blockoff[t] = sm[t] - v;
    if (t == NB - 1) g_blockoff[NB] = sm[t];
}

__global__ void scan3_kernel() {
    int i = blockIdx.x * blockDim.x + threadIdx.x;
    if (i == 0) g_rowptr[RN] = g_blockoff[NB];
    if (i >= RN) return;
    int excl = g_rowptr[i] - g_deg_in[i] + g_blockoff[i >> 10];
    g_rowptr[i] = excl;
    g_pos[i]    = excl;
}

__global__ void fill_csr_kernel(const int* __restrict__ src,
                                const int* __restrict__ dst) {
    int e = blockIdx.x * blockDim.x + threadIdx.x;
    if (e >= EE) return;
    int r = blockIdx.y;
    int i = r * EE + e;
    int p = atomicAdd(&g_pos[r * NN + dst[i]], 1);
    g_colsrc[p] = src[i];
}

// transpose + bf16-split W: [r][K=128][Ndim] fp32 -> [r][Ndim][128] bf16 hi/lo
template <int Ndim>
__global__ void wsplit_kernel(const float* __restrict__ W,
                              __nv_bfloat16* __restrict__ Thi,
                              __nv_bfloat16* __restrict__ Tlo) {
    int r = blockIdx.y;
    int i = blockIdx.x * 256 + threadIdx.x;
    if (i >= 128 * Ndim) return;
    int k = i / Ndim, n = i % Ndim;
    float v = W[((size_t)r * 128 + k) * Ndim + n];
    __nv_bfloat16 hi = __float2bfloat16_rn(v);
    __nv_bfloat16 lo = __float2bfloat16_rn(v - __bfloat162float(hi));
    Thi[((size_t)r * Ndim + n) * 128 + k] = hi;
    Tlo[((size_t)r * Ndim + n) * 128 + k] = lo;
}

// ---------------- HMMA bf16x2 3-term GEMM: Y[r] = A @ W[r] ------------------
// A fp32 split hi/lo on the fly into swizzled SMEM; W^T bf16 hi/lo same layout.
// Full K resident; 8 k-steps of ldmatrix + mma.sync m16n8k16. Y stored fp16.
template <int N, int LAYER>
__global__ void __launch_bounds__(256)
mma_gemm_kernel(const float* __restrict__ xin) {
    extern __shared__ char smem[];
    const float* A = (LAYER == 0) ? xin : g_H;
    const __nv_bfloat16* Whi = (LAYER == 0) ? g_W1T_hi : g_W2T_hi;
    const __nv_bfloat16* Wlo = (LAYER == 0) ? g_W1T_lo : g_W2T_lo;
    __half* Y = (LAYER == 0) ? g_Y1h : g_Y2h;

    constexpr int A_BYTES = 128 * 256;
    constexpr int B_BYTES = N * 256;
    constexpr int OFF_AHI = 0;
    constexpr int OFF_ALO = A_BYTES;
    constexpr int OFF_BHI = 2 * A_BYTES;
    constexpr int OFF_BLO = 2 * A_BYTES + B_BYTES;

    const int t = threadIdx.x;
    const int r = blockIdx.y;
    const int row0 = blockIdx.x * 128;

    // ---- B: copy bf16 hi/lo granules into swizzled SMEM ----
    {
        const uint4* bh = (const uint4*)(Whi + (size_t)r * N * 128);
        const uint4* bl = (const uint4*)(Wlo + (size_t)r * N * 128);
        #pragma unroll
        for (int i = t; i < N * 16; i += 256) {
            int n = i >> 4, g = i & 15;
            uint32_t off = n * 256 + ((g ^ (n & 7)) << 4);
            *(uint4*)(smem + OFF_BHI + off) = bh[i];
            *(uint4*)(smem + OFF_BLO + off) = bl[i];
        }
    }
    // ---- A: load fp32, split to bf16 hi/lo, swizzled store ----
    #pragma unroll
    for (int i = t; i < 128 * 16; i += 256) {
        int m = i >> 4, g = i & 15;
        int grow = row0 + m;
        float4 v0 = make_float4(0.f, 0.f, 0.f, 0.f);
        float4 v1 = make_float4(0.f, 0.f, 0.f, 0.f);
        if (grow < NN) {
            const float4* ap = (const float4*)(A + (size_t)grow * 128 + g * 8);
            v0 = ap[0]; v1 = ap[1];
        }
        __nv_bfloat162 h0 = __floats2bfloat162_rn(v0.x, v0.y);
        __nv_bfloat162 h1 = __floats2bfloat162_rn(v0.z, v0.w);
        __nv_bfloat162 h2 = __floats2bfloat162_rn(v1.x, v1.y);
        __nv_bfloat162 h3 = __floats2bfloat162_rn(v1.z, v1.w);
        __nv_bfloat162 l0 = __floats2bfloat162_rn(v0.x - __bfloat162float(h0.x),
                                                  v0.y - __bfloat162float(h0.y));
        __nv_bfloat162 l1 = __floats2bfloat162_rn(v0.z - __bfloat162float(h1.x),
                                                  v0.w - __bfloat162float(h1.y));
        __nv_bfloat162 l2 = __floats2bfloat162_rn(v1.x - __bfloat162float(h2.x),
                                                  v1.y - __bfloat162float(h2.y));
        __nv_bfloat162 l3 = __floats2bfloat162_rn(v1.z - __bfloat162float(h3.x),
                                                  v1.w - __bfloat162float(h3.y));
        uint32_t off = m * 256 + ((g ^ (m & 7)) << 4);
        *(uint4*)(smem + OFF_AHI + off) = make_uint4(b2u(h0), b2u(h1), b2u(h2), b2u(h3));
        *(uint4*)(smem + OFF_ALO + off) = make_uint4(b2u(l0), b2u(l1), b2u(l2), b2u(l3));
    }
    __syncthreads();

    // ---- warp tiling ----
    constexpr int WM = (N == 128) ? 64 : 32;    // warp M tile
    constexpr int WN = 32;                      // warp N tile
    constexpr int WX = N / WN;                  // warps along N
    constexpr int MI = WM / 16, NI = WN / 8;
    const int wid = t >> 5, lane = t & 31;
    const int wm0 = (wid / WX) * WM;
    const int wn0 = (wid % WX) * WN;

    float acc[MI][NI][4];
    #pragma unroll
    for (int mi = 0; mi < MI; mi++)
        #pragma unroll
        for (int ni = 0; ni < NI; ni++)
            #pragma unroll
            for (int q = 0; q < 4; q++) acc[mi][ni][q] = 0.f;

    const uint32_t sbase = smem_u32(smem);
    const int a_row = (lane & 15);
    const int a_kg  = (lane >> 4);
    const int b_n   = (lane & 7);
    const int b_kg  = ((lane >> 3) & 1);

    #pragma unroll
    for (int ks = 0; ks < 8; ks++) {
        uint32_t ah[MI][4], al[MI][4];
        #pragma unroll
        for (int mi = 0; mi < MI; mi++) {
            int row = wm0 + mi * 16 + a_row;
            int kg  = ks * 2 + a_kg;
            uint32_t off = row * 256 + ((kg ^ (row & 7)) << 4);
            ldsm_x4(ah[mi][0], ah[mi][1], ah[mi][2], ah[mi][3],
                    sbase + OFF_AHI + off);
            ldsm_x4(al[mi][0], al[mi][1], al[mi][2], al[mi][3],
                    sbase + OFF_ALO + off);
        }
        uint32_t bh[NI][2], bl[NI][2];
        #pragma unroll
        for (int ni = 0; ni < NI; ni++) {
            int n  = wn0 + ni * 8 + b_n;
            int kg = ks * 2 + b_kg;
            uint32_t off = n * 256 + ((kg ^ (n & 7)) << 4);
            ldsm_x2(bh[ni][0], bh[ni][1], sbase + OFF_BHI + off);
            ldsm_x2(bl[ni][0], bl[ni][1], sbase + OFF_BLO + off);
        }
        #pragma unroll
        for (int mi = 0; mi < MI; mi++)
            #pragma unroll
            for (int ni = 0; ni < NI; ni++) {
                mma_bf16(acc[mi][ni], ah[mi], bh[ni]);  // hi*hi
                mma_bf16(acc[mi][ni], ah[mi], bl[ni]);  // hi*lo
                mma_bf16(acc[mi][ni], al[mi], bh[ni]);  // lo*hi
            }
    }

    // ---- epilogue: write fp16 Y ----
    #pragma unroll
    for (int mi = 0; mi < MI; mi++) {
        int m0 = row0 + wm0 + mi * 16 + (lane >> 2);
        #pragma unroll
        for (int ni = 0; ni < NI; ni++) {
            int n = wn0 + ni * 8 + 2 * (lane & 3);
            if (m0 < NN)
                *(__half2*)&Y[((size_t)r * NN + m0) * N + n] =
                    __floats2half2_rn(acc[mi][ni][0], acc[mi][ni][1]);
            if (m0 + 8 < NN)
                *(__half2*)&Y[((size_t)r * NN + m0 + 8) * N + n] =
                    __floats2half2_rn(acc[mi][ni][2], acc[mi][ni][3]);
        }
    }
}

// ---------------- aggregation (gather via CSR), onorm folded per-edge -------
__global__ void agg1_kernel(const float* __restrict__ b1) {
    int gt   = blockIdx.x * blockDim.x + threadIdx.x;
    int n    = gt >> 5;
    int lane = gt & 31;
    if (n >= NN) return;

    float4 acc = make_float4(0.f, 0.f, 0.f, 0.f);
    #pragma unroll
    for (int r = 0; r < RR; r++) {
        int key = r * NN + n;
        int beg = g_rowptr[key];
        int end = g_rowptr[key + 1];
        float4 s = make_float4(0.f, 0.f, 0.f, 0.f);
        for (int j = beg; j < end; j++) {
            int sn = g_colsrc[j];
            float on = g_onorm[r * NN + sn];
            uint2 u = *(const uint2*)&g_Y1h[((size_t)r * NN + sn) * DHID + lane * 4];
            float2 f0 = __half22float2(*reinterpret_cast<const __half2*>(&u.x));
            float2 f1 = __half22float2(*reinterpret_cast<const __half2*>(&u.y));
            s.x += on * f0.x; s.y += on * f0.y;
            s.z += on * f1.x; s.w += on * f1.y;
        }
        float inn = g_inorm[key];
        acc.x += inn * s.x; acc.y += inn * s.y;
        acc.z += inn * s.z; acc.w += inn * s.w;
    }
    int col = lane * 4;
    acc.x += b1[col + 0] + b1[DHID + col + 0] + b1[2 * DHID + col + 0];
    acc.y += b1[col + 1] + b1[DHID + col + 1] + b1[2 * DHID + col + 1];
    acc.z += b1[col + 2] + b1[DHID + col + 2] + b1[2 * DHID + col + 2];
    acc.w += b1[col + 3] + b1[DHID + col + 3] + b1[2 * DHID + col + 3];
    acc.x = fmaxf(acc.x, 0.f); acc.y = fmaxf(acc.y, 0.f);
    acc.z = fmaxf(acc.z, 0.f); acc.w = fmaxf(acc.w, 0.f);
    *(float4*)&g_H[(size_t)n * DHID + col] = acc;
}

__global__ void agg2_kernel(const float* __restrict__ b2,
                            float* __restrict__ out) {
    int gt   = blockIdx.x * blockDim.x + threadIdx.x;
    int n    = gt >> 5;
    int lane = gt & 31;
    if (n >= NN) return;

    float2 acc = make_float2(0.f, 0.f);
    #pragma unroll
    for (int r = 0; r < RR; r++) {
        int key = r * NN + n;
        int beg = g_rowptr[key];
        int end = g_rowptr[key + 1];
        float2 s = make_float2(0.f, 0.f);
        for (int j = beg; j < end; j++) {
            int sn = g_colsrc[j];
            float on = g_onorm[r * NN + sn];
            uint32_t u = *(const uint32_t*)&g_Y2h[((size_t)r * NN + sn) * DOUT + lane * 2];
            float2 f = __half22float2(*reinterpret_cast<const __half2*>(&u));
            s.x += on * f.x; s.y += on * f.y;
        }
        float inn = g_inorm[key];
        acc.x += inn * s.x; acc.y += inn * s.y;
    }
    int col = lane * 2;
    acc.x += b2[col + 0] + b2[DOUT + col + 0] + b2[2 * DOUT + col + 0];
    acc.y += b2[col + 1] + b2[DOUT + col + 1] + b2[2 * DOUT + col + 1];
    *(float2*)&out[(size_t)n * DOUT + col] = acc;
}

// ---------------- launch -----------------------------------------------------
extern "C" void kernel_launch(void* const* d_in, const int* in_sizes, int n_in,
                              void* d_out, int out_size) {
    const float* x   = (const float*)d_in[0];
    const float* W1  = (const float*)d_in[1];
    const float* b1  = (const float*)d_in[2];
    const float* W2  = (const float*)d_in[3];
    const float* b2  = (const float*)d_in[4];
    const int*   src = (const int*)d_in[5];
    const int*   dst = (const int*)d_in[6];
    float*       out = (float*)d_out;

    __nv_bfloat16 *w1hi, *w1lo, *w2hi, *w2lo;
    cudaGetSymbolAddress((void**)&w1hi, g_W1T_hi);
    cudaGetSymbolAddress((void**)&w1lo, g_W1T_lo);
    cudaGetSymbolAddress((void**)&w2hi, g_W2T_hi);
    cudaGetSymbolAddress((void**)&w2lo, g_W2T_lo);

    // one-time host resources (no device memory involved)
    static cudaStream_t s2 = nullptr;
    static cudaEvent_t  evFork = nullptr, evPre = nullptr;
    if (s2 == nullptr) {
        cudaStreamCreateWithFlags(&s2, cudaStreamNonBlocking);
        cudaEventCreateWithFlags(&evFork, cudaEventDisableTiming);
        cudaEventCreateWithFlags(&evPre,  cudaEventDisableTiming);
    }

    const int SMEM1 = 2 * (128 * 256) + 2 * (128 * 256);  // 131072
    const int SMEM2 = 2 * (128 * 256) + 2 * ( 64 * 256);  //  98304
    cudaFuncSetAttribute(mma_gemm_kernel<128, 0>,
                         cudaFuncAttributeMaxDynamicSharedMemorySize, SMEM1);
    cudaFuncSetAttribute(mma_gemm_kernel<64, 1>,
                         cudaFuncAttributeMaxDynamicSharedMemorySize, SMEM2);

    // ---- fork: CSR/norm preprocessing on side stream ----
    cudaEventRecord(evFork, 0);
    cudaStreamWaitEvent(s2, evFork, 0);
    zero_deg_kernel <<<(RN + 255) / 256, 256, 0, s2>>>();
    count_deg_kernel<<<dim3((EE + 255) / 256, RR), 256, 0, s2>>>(src, dst);
    norm_kernel     <<<(RN + 255) / 256, 256, 0, s2>>>();
    scan1_kernel    <<<NB, 1024, 0, s2>>>();
    scan2_kernel    <<<1, 256, 0, s2>>>();
    scan3_kernel    <<<(RN + 255) / 256, 256, 0, s2>>>();
    fill_csr_kernel <<<dim3((EE + 255) / 256, RR), 256, 0, s2>>>(src, dst);
    cudaEventRecord(evPre, s2);

    // ---- main stream: weight split + layer-1 GEMM (independent of graph) ----
    wsplit_kernel<DHID><<<dim3((128 * DHID + 255) / 256, RR), 256>>>(W1, w1hi, w1lo);
    wsplit_kernel<DOUT><<<dim3((128 * DOUT + 255) / 256, RR), 256>>>(W2, w2hi, w2lo);
    mma_gemm_kernel<128, 0><<<dim3((NN + 127) / 128, RR), 256, SMEM1>>>(x);

    // ---- join: aggregation needs CSR + norms ----
    cudaStreamWaitEvent(0, evPre, 0);
    agg1_kernel<<<(NN * 32 + 255) / 256, 256>>>(b1);

    // layer 2
    mma_gemm_kernel<64, 1><<<dim3((NN + 127) / 128, RR), 256, SMEM2>>>(nullptr);
    agg2_kernel<<<(NN * 32 + 255) / 256, 256>>>(b2, out);
}

// round 14
// speedup vs baseline: 3.5004x; 1.0188x over previous
#include <cuda_runtime.h>
#include <cuda_bf16.h>
#include <cuda_fp16.h>
#include <cstdint>

#define RR   3
#define NN   50000
#define EE   200000
#define RN   (RR*NN)
#define RE   (RR*EE)
#define DIN  128
#define DHID 128
#define DOUT 64
#define NB   ((RN + 1023) / 1024)   // 147 scan blocks

// ---------------- scratch (device globals; no allocation allowed) ----------
__device__ int   g_deg_out[RN];
__device__ int   g_deg_in [RN];
__device__ float g_onorm  [RN];
__device__ float g_inorm  [RN];
__device__ int   g_rowptr [RN + 1];
__device__ int   g_pos    [RN];
__device__ int   g_colsrc [RE];
__device__ int   g_blocksum[NB];
__device__ int   g_blockoff[NB + 1];
__device__ __half g_Y1h[(size_t)RN * DHID];  // onorm-scaled transformed feats (fp16)
__device__ __half g_Hh [(size_t)NN * DHID];  // hidden after relu (fp16)
__device__ __half g_Y2h[(size_t)RN * DOUT];
__device__ __nv_bfloat16 g_W1T_hi[RR * DHID * DIN]; // W1^T [r][n][k], bf16 hi/lo
__device__ __nv_bfloat16 g_W1T_lo[RR * DHID * DIN];
__device__ __nv_bfloat16 g_W2T_hi[RR * DOUT * DHID];
__device__ __nv_bfloat16 g_W2T_lo[RR * DOUT * DHID];

// ---------------- ptx helpers ------------------------------------------------
__device__ __forceinline__ uint32_t smem_u32(const void* p) {
    uint32_t a;
    asm("{ .reg .u64 t; cvta.to.shared.u64 t, %1; cvt.u32.u64 %0, t; }"
        : "=r"(a) : "l"(p));
    return a;
}
__device__ __forceinline__ void ldsm_x4(uint32_t& r0, uint32_t& r1,
                                        uint32_t& r2, uint32_t& r3, uint32_t a) {
    asm volatile("ldmatrix.sync.aligned.m8n8.x4.shared.b16 {%0,%1,%2,%3}, [%4];"
                 : "=r"(r0), "=r"(r1), "=r"(r2), "=r"(r3) : "r"(a));
}
__device__ __forceinline__ void ldsm_x2(uint32_t& r0, uint32_t& r1, uint32_t a) {
    asm volatile("ldmatrix.sync.aligned.m8n8.x2.shared.b16 {%0,%1}, [%2];"
                 : "=r"(r0), "=r"(r1) : "r"(a));
}
__device__ __forceinline__ void mma_bf16(float* d, const uint32_t* a,
                                         const uint32_t* b) {
    asm volatile(
        "mma.sync.aligned.m16n8k16.row.col.f32.bf16.bf16.f32 "
        "{%0,%1,%2,%3}, {%4,%5,%6,%7}, {%8,%9}, {%0,%1,%2,%3};"
        : "+f"(d[0]), "+f"(d[1]), "+f"(d[2]), "+f"(d[3])
        : "r"(a[0]), "r"(a[1]), "r"(a[2]), "r"(a[3]), "r"(b[0]), "r"(b[1]));
}
__device__ __forceinline__ uint32_t b2u(__nv_bfloat162 v) {
    return *reinterpret_cast<uint32_t*>(&v);
}

// ---------------- graph preprocessing ---------------------------------------
__global__ void zero_deg_kernel() {
    int i = blockIdx.x * blockDim.x + threadIdx.x;
    if (i < RN) { g_deg_out[i] = 0; g_deg_in[i] = 0; }
}

__global__ void count_deg_kernel(const int* __restrict__ src,
                                 const int* __restrict__ dst) {
    int e = blockIdx.x * blockDim.x + threadIdx.x;
    if (e >= EE) return;
    int r = blockIdx.y;
    int i = r * EE + e;
    atomicAdd(&g_deg_out[r * NN + src[i]], 1);
    atomicAdd(&g_deg_in [r * NN + dst[i]], 1);
}

__global__ void onorm_kernel() {
    int i = blockIdx.x * blockDim.x + threadIdx.x;
    if (i >= RN) return;
    int od = g_deg_out[i]; if (od < 1) od = 1;
    g_onorm[i] = rsqrtf((float)od);
}

__global__ void scan1_kernel() {
    __shared__ int sm[1024];
    const int t = threadIdx.x;
    const int i = blockIdx.x * 1024 + t;
    int v = (i < RN) ? g_deg_in[i] : 0;
    sm[t] = v;
    __syncthreads();
    #pragma unroll
    for (int off = 1; off < 1024; off <<= 1) {
        int u = (t >= off) ? sm[t - off] : 0;
        __syncthreads();
        sm[t] += u;
        __syncthreads();
    }
    if (i < RN) g_rowptr[i] = sm[t];
    if (t == 1023) g_blocksum[blockIdx.x] = sm[1023];
}

__global__ void scan2_kernel() {
    __shared__ int sm[256];
    const int t = threadIdx.x;
    int v = (t < NB) ? g_blocksum[t] : 0;
    sm[t] = v;
    __syncthreads();
    #pragma unroll
    for (int off = 1; off < 256; off <<= 1) {
        int u = (t >= off) ? sm[t - off] : 0;
        __syncthreads();
        sm[t] += u;
        __syncthreads();
    }
    if (t < NB) g_blockoff[t] = sm[t] - v;
    if (t == NB - 1) g_blockoff[NB] = sm[t];
}

// scan fixup + inorm (deg_in already in hand)
__global__ void scan3_kernel() {
    int i = blockIdx.x * blockDim.x + threadIdx.x;
    if (i == 0) g_rowptr[RN] = g_blockoff[NB];
    if (i >= RN) return;
    int d = g_deg_in[i];
    int excl = g_rowptr[i] - d + g_blockoff[i >> 10];
    g_rowptr[i] = excl;
    g_pos[i]    = excl;
    g_inorm[i]  = rsqrtf((float)(d < 1 ? 1 : d));
}

__global__ void fill_csr_kernel(const int* __restrict__ src,
                                const int* __restrict__ dst) {
    int e = blockIdx.x * blockDim.x + threadIdx.x;
    if (e >= EE) return;
    int r = blockIdx.y;
    int i = r * EE + e;
    int p = atomicAdd(&g_pos[r * NN + dst[i]], 1);
    g_colsrc[p] = src[i];
}

// transpose + bf16-split W: [r][K=128][Ndim] fp32 -> [r][Ndim][128] bf16 hi/lo
template <int Ndim>
__global__ void wsplit_kernel(const float* __restrict__ W,
                              __nv_bfloat16* __restrict__ Thi,
                              __nv_bfloat16* __restrict__ Tlo) {
    int r = blockIdx.y;
    int i = blockIdx.x * 256 + threadIdx.x;
    if (i >= 128 * Ndim) return;
    int k = i / Ndim, n = i % Ndim;
    float v = W[((size_t)r * 128 + k) * Ndim + n];
    __nv_bfloat16 hi = __float2bfloat16_rn(v);
    __nv_bfloat16 lo = __float2bfloat16_rn(v - __bfloat162float(hi));
    Thi[((size_t)r * Ndim + n) * 128 + k] = hi;
    Tlo[((size_t)r * Ndim + n) * 128 + k] = lo;
}

// ---------------- HMMA bf16x2 3-term GEMM: Y[r] = onorm_r ⊙ (A @ W[r]) ------
// A split hi/lo on the fly into swizzled SMEM; W^T bf16 hi/lo same layout.
// Full K resident; 8 k-steps of ldmatrix + mma.sync. Epilogue scales rows by
// onorm and stores fp16.
template <int N, int LAYER>
__global__ void __launch_bounds__(256)
mma_gemm_kernel(const float* __restrict__ xin) {
    extern __shared__ char smem[];
    const __nv_bfloat16* Whi = (LAYER == 0) ? g_W1T_hi : g_W2T_hi;
    const __nv_bfloat16* Wlo = (LAYER == 0) ? g_W1T_lo : g_W2T_lo;
    __half* Y = (LAYER == 0) ? g_Y1h : g_Y2h;

    constexpr int A_BYTES = 128 * 256;
    constexpr int B_BYTES = N * 256;
    constexpr int OFF_AHI = 0;
    constexpr int OFF_ALO = A_BYTES;
    constexpr int OFF_BHI = 2 * A_BYTES;
    constexpr int OFF_BLO = 2 * A_BYTES + B_BYTES;

    const int t = threadIdx.x;
    const int r = blockIdx.y;
    const int row0 = blockIdx.x * 128;

    // ---- B: copy bf16 hi/lo granules into swizzled SMEM ----
    {
        const uint4* bh = (const uint4*)(Whi + (size_t)r * N * 128);
        const uint4* bl = (const uint4*)(Wlo + (size_t)r * N * 128);
        #pragma unroll
        for (int i = t; i < N * 16; i += 256) {
            int n = i >> 4, g = i & 15;
            uint32_t off = n * 256 + ((g ^ (n & 7)) << 4);
            *(uint4*)(smem + OFF_BHI + off) = bh[i];
            *(uint4*)(smem + OFF_BLO + off) = bl[i];
        }
    }
    // ---- A: load (fp32 layer0 / fp16 layer1), split to bf16 hi/lo ----
    #pragma unroll
    for (int i = t; i < 128 * 16; i += 256) {
        int m = i >> 4, g = i & 15;
        int grow = row0 + m;
        float4 v0 = make_float4(0.f, 0.f, 0.f, 0.f);
        float4 v1 = make_float4(0.f, 0.f, 0.f, 0.f);
        if (grow < NN) {
            if (LAYER == 0) {
                const float4* ap = (const float4*)(xin + (size_t)grow * 128 + g * 8);
                v0 = ap[0]; v1 = ap[1];
            } else {
                uint4 u = *(const uint4*)(g_Hh + (size_t)grow * 128 + g * 8);
                float2 f0 = __half22float2(*reinterpret_cast<const __half2*>(&u.x));
                float2 f1 = __half22float2(*reinterpret_cast<const __half2*>(&u.y));
                float2 f2 = __half22float2(*reinterpret_cast<const __half2*>(&u.z));
                float2 f3 = __half22float2(*reinterpret_cast<const __half2*>(&u.w));
                v0 = make_float4(f0.x, f0.y, f1.x, f1.y);
                v1 = make_float4(f2.x, f2.y, f3.x, f3.y);
            }
        }
        __nv_bfloat162 h0 = __floats2bfloat162_rn(v0.x, v0.y);
        __nv_bfloat162 h1 = __floats2bfloat162_rn(v0.z, v0.w);
        __nv_bfloat162 h2 = __floats2bfloat162_rn(v1.x, v1.y);
        __nv_bfloat162 h3 = __floats2bfloat162_rn(v1.z, v1.w);
        __nv_bfloat162 l0 = __floats2bfloat162_rn(v0.x - __bfloat162float(h0.x),
                                                  v0.y - __bfloat162float(h0.y));
        __nv_bfloat162 l1 = __floats2bfloat162_rn(v0.z - __bfloat162float(h1.x),
                                                  v0.w - __bfloat162float(h1.y));
        __nv_bfloat162 l2 = __floats2bfloat162_rn(v1.x - __bfloat162float(h2.x),
                                                  v1.y - __bfloat162float(h2.y));
        __nv_bfloat162 l3 = __floats2bfloat162_rn(v1.z - __bfloat162float(h3.x),
                                                  v1.w - __bfloat162float(h3.y));
        uint32_t off = m * 256 + ((g ^ (m & 7)) << 4);
        *(uint4*)(smem + OFF_AHI + off) = make_uint4(b2u(h0), b2u(h1), b2u(h2), b2u(h3));
        *(uint4*)(smem + OFF_ALO + off) = make_uint4(b2u(l0), b2u(l1), b2u(l2), b2u(l3));
    }
    __syncthreads();

    // ---- warp tiling ----
    constexpr int WM = (N == 128) ? 64 : 32;    // warp M tile
    constexpr int WN = 32;                      // warp N tile
    constexpr int WX = N / WN;                  // warps along N
    constexpr int MI = WM / 16, NI = WN / 8;
    const int wid = t >> 5, lane = t & 31;
    const int wm0 = (wid / WX) * WM;
    const int wn0 = (wid % WX) * WN;

    float acc[MI][NI][4];
    #pragma unroll
    for (int mi = 0; mi < MI; mi++)
        #pragma unroll
        for (int ni = 0; ni < NI; ni++)
            #pragma unroll
            for (int q = 0; q < 4; q++) acc[mi][ni][q] = 0.f;

    const uint32_t sbase = smem_u32(smem);
    const int a_row = (lane & 15);
    const int a_kg  = (lane >> 4);
    const int b_n   = (lane & 7);
    const int b_kg  = ((lane >> 3) & 1);

    #pragma unroll
    for (int ks = 0; ks < 8; ks++) {
        uint32_t ah[MI][4], al[MI][4];
        #pragma unroll
        for (int mi = 0; mi < MI; mi++) {
            int row = wm0 + mi * 16 + a_row;
            int kg  = ks * 2 + a_kg;
            uint32_t off = row * 256 + ((kg ^ (row & 7)) << 4);
            ldsm_x4(ah[mi][0], ah[mi][1], ah[mi][2], ah[mi][3],
                    sbase + OFF_AHI + off);
            ldsm_x4(al[mi][0], al[mi][1], al[mi][2], al[mi][3],
                    sbase + OFF_ALO + off);
        }
        uint32_t bh[NI][2], bl[NI][2];
        #pragma unroll
        for (int ni = 0; ni < NI; ni++) {
            int n  = wn0 + ni * 8 + b_n;
            int kg = ks * 2 + b_kg;
            uint32_t off = n * 256 + ((kg ^ (n & 7)) << 4);
            ldsm_x2(bh[ni][0], bh[ni][1], sbase + OFF_BHI + off);
            ldsm_x2(bl[ni][0], bl[ni][1], sbase + OFF_BLO + off);
        }
        #pragma unroll
        for (int mi = 0; mi < MI; mi++)
            #pragma unroll
            for (int ni = 0; ni < NI; ni++) {
                mma_bf16(acc[mi][ni], ah[mi], bh[ni]);  // hi*hi
                mma_bf16(acc[mi][ni], ah[mi], bl[ni]);  // hi*lo
                mma_bf16(acc[mi][ni], al[mi], bh[ni]);  // lo*hi
            }
    }

    // ---- epilogue: scale rows by onorm, write fp16 Y ----
    #pragma unroll
    for (int mi = 0; mi < MI; mi++) {
        int m0 = row0 + wm0 + mi * 16 + (lane >> 2);
        float on0 = (m0 < NN)     ? g_onorm[r * NN + m0]     : 0.f;
        float on1 = (m0 + 8 < NN) ? g_onorm[r * NN + m0 + 8] : 0.f;
        #pragma unroll
        for (int ni = 0; ni < NI; ni++) {
            int n = wn0 + ni * 8 + 2 * (lane & 3);
            if (m0 < NN)
                *(__half2*)&Y[((size_t)r * NN + m0) * N + n] =
                    __floats2half2_rn(acc[mi][ni][0] * on0, acc[mi][ni][1] * on0);
            if (m0 + 8 < NN)
                *(__half2*)&Y[((size_t)r * NN + m0 + 8) * N + n] =
                    __floats2half2_rn(acc[mi][ni][2] * on1, acc[mi][ni][3] * on1);
        }
    }
}

// ---------------- aggregation (gather via CSR, onorm pre-folded) ------------
__global__ void agg1_kernel(const float* __restrict__ b1) {
    int gt   = blockIdx.x * blockDim.x + threadIdx.x;
    int n    = gt >> 5;
    int lane = gt & 31;
    if (n >= NN) return;

    float4 acc = make_float4(0.f, 0.f, 0.f, 0.f);
    #pragma unroll
    for (int r = 0; r < RR; r++) {
        int key = r * NN + n;
        int beg = g_rowptr[key];
        int end = g_rowptr[key + 1];
        const __half* Yr = g_Y1h + (size_t)r * NN * DHID;
        float4 s = make_float4(0.f, 0.f, 0.f, 0.f);
        int j = beg;
        for (; j + 1 < end; j += 2) {
            int sn0 = g_colsrc[j];
            int sn1 = g_colsrc[j + 1];
            uint2 u0 = *(const uint2*)&Yr[(size_t)sn0 * DHID + lane * 4];
            uint2 u1 = *(const uint2*)&Yr[(size_t)sn1 * DHID + lane * 4];
            float2 a0 = __half22float2(*reinterpret_cast<const __half2*>(&u0.x));
            float2 a1 = __half22float2(*reinterpret_cast<const __half2*>(&u0.y));
            float2 c0 = __half22float2(*reinterpret_cast<const __half2*>(&u1.x));
            float2 c1 = __half22float2(*reinterpret_cast<const __half2*>(&u1.y));
            s.x += a0.x + c0.x; s.y += a0.y + c0.y;
            s.z += a1.x + c1.x; s.w += a1.y + c1.y;
        }
        if (j < end) {
            int sn = g_colsrc[j];
            uint2 u = *(const uint2*)&Yr[(size_t)sn * DHID + lane * 4];
            float2 a0 = __half22float2(*reinterpret_cast<const __half2*>(&u.x));
            float2 a1 = __half22float2(*reinterpret_cast<const __half2*>(&u.y));
            s.x += a0.x; s.y += a0.y; s.z += a1.x; s.w += a1.y;
        }
        float inn = g_inorm[key];
        acc.x += inn * s.x; acc.y += inn * s.y;
        acc.z += inn * s.z; acc.w += inn * s.w;
    }
    int col = lane * 4;
    acc.x += b1[col + 0] + b1[DHID + col + 0] + b1[2 * DHID + col + 0];
    acc.y += b1[col + 1] + b1[DHID + col + 1] + b1[2 * DHID + col + 1];
    acc.z += b1[col + 2] + b1[DHID + col + 2] + b1[2 * DHID + col + 2];
    acc.w += b1[col + 3] + b1[DHID + col + 3] + b1[2 * DHID + col + 3];
    acc.x = fmaxf(acc.x, 0.f); acc.y = fmaxf(acc.y, 0.f);
    acc.z = fmaxf(acc.z, 0.f); acc.w = fmaxf(acc.w, 0.f);
    *(uint2*)&g_Hh[(size_t)n * DHID + col] = make_uint2(
        *(uint32_t*)&(__half2&)*(__half2[]){__floats2half2_rn(acc.x, acc.y)},
        *(uint32_t*)&(__half2&)*(__half2[]){__floats2half2_rn(acc.z, acc.w)});
}

__global__ void agg2_kernel(const float* __restrict__ b2,
                            float* __restrict__ out) {
    int gt   = blockIdx.x * blockDim.x + threadIdx.x;
    int n    = gt >> 5;
    int lane = gt & 31;
    if (n >= NN) return;

    float2 acc = make_float2(0.f, 0.f);
    #pragma unroll
    for (int r = 0; r < RR; r++) {
        int key = r * NN + n;
        int beg = g_rowptr[key];
        int end = g_rowptr[key + 1];
        const __half* Yr = g_Y2h + (size_t)r * NN * DOUT;
        float2 s = make_float2(0.f, 0.f);
        int j = beg;
        for (; j + 1 < end; j += 2) {
            int sn0 = g_colsrc[j];
            int sn1 = g_colsrc[j + 1];
            uint32_t u0 = *(const uint32_t*)&Yr[(size_t)sn0 * DOUT + lane * 2];
            uint32_t u1 = *(const uint32_t*)&Yr[(size_t)sn1 * DOUT + lane * 2];
            float2 f0 = __half22float2(*reinterpret_cast<const __half2*>(&u0));
            float2 f1 = __half22float2(*reinterpret_cast<const __half2*>(&u1));
            s.x += f0.x + f1.x; s.y += f0.y + f1.y;
        }
        if (j < end) {
            int sn = g_colsrc[j];
            uint32_t u = *(const uint32_t*)&Yr[(size_t)sn * DOUT + lane * 2];
            float2 f = __half22float2(*reinterpret_cast<const __half2*>(&u));
            s.x += f.x; s.y += f.y;
        }
        float inn = g_inorm[key];
        acc.x += inn * s.x; acc.y += inn * s.y;
    }
    int col = lane * 2;
    acc.x += b2[col + 0] + b2[DOUT + col + 0] + b2[2 * DOUT + col + 0];
    acc.y += b2[col + 1] + b2[DOUT + col + 1] + b2[2 * DOUT + col + 1];
    *(float2*)&out[(size_t)n * DOUT + col] = acc;
}

// ---------------- launch -----------------------------------------------------
extern "C" void kernel_launch(void* const* d_in, const int* in_sizes, int n_in,
                              void* d_out, int out_size) {
    const float* x   = (const float*)d_in[0];
    const float* W1  = (const float*)d_in[1];
    const float* b1  = (const float*)d_in[2];
    const float* W2  = (const float*)d_in[3];
    const float* b2  = (const float*)d_in[4];
    const int*   src = (const int*)d_in[5];
    const int*   dst = (const int*)d_in[6];
    float*       out = (float*)d_out;

    __nv_bfloat16 *w1hi, *w1lo, *w2hi, *w2lo;
    cudaGetSymbolAddress((void**)&w1hi, g_W1T_hi);
    cudaGetSymbolAddress((void**)&w1lo, g_W1T_lo);
    cudaGetSymbolAddress((void**)&w2hi, g_W2T_hi);
    cudaGetSymbolAddress((void**)&w2lo, g_W2T_lo);

    // one-time host resources (no device memory involved)
    static cudaStream_t s2 = nullptr;
    static cudaEvent_t  evFork = nullptr, evNorm = nullptr, evPre = nullptr;
    if (s2 == nullptr) {
        cudaStreamCreateWithFlags(&s2, cudaStreamNonBlocking);
        cudaEventCreateWithFlags(&evFork, cudaEventDisableTiming);
        cudaEventCreateWithFlags(&evNorm, cudaEventDisableTiming);
        cudaEventCreateWithFlags(&evPre,  cudaEventDisableTiming);
    }

    const int SMEM1 = 2 * (128 * 256) + 2 * (128 * 256);  // 131072
    const int SMEM2 = 2 * (128 * 256) + 2 * ( 64 * 256);  //  98304
    cudaFuncSetAttribute(mma_gemm_kernel<128, 0>,
                         cudaFuncAttributeMaxDynamicSharedMemorySize, SMEM1);
    cudaFuncSetAttribute(mma_gemm_kernel<64, 1>,
                         cudaFuncAttributeMaxDynamicSharedMemorySize, SMEM2);

    // ---- fork: graph preprocessing on side stream ----
    cudaEventRecord(evFork, 0);
    cudaStreamWaitEvent(s2, evFork, 0);
    zero_deg_kernel <<<(RN + 255) / 256, 256, 0, s2>>>();
    count_deg_kernel<<<dim3((EE + 255) / 256, RR), 256, 0, s2>>>(src, dst);
    onorm_kernel    <<<(RN + 255) / 256, 256, 0, s2>>>();
    cudaEventRecord(evNorm, s2);                     // onorm ready for GEMM1
    scan1_kernel    <<<NB, 1024, 0, s2>>>();
    scan2_kernel    <<<1, 256, 0, s2>>>();
    scan3_kernel    <<<(RN + 255) / 256, 256, 0, s2>>>();  // + inorm
    fill_csr_kernel <<<dim3((EE + 255) / 256, RR), 256, 0, s2>>>(src, dst);
    cudaEventRecord(evPre, s2);

    // ---- main stream: weight split overlaps count/norm ----
    wsplit_kernel<DHID><<<dim3((128 * DHID + 255) / 256, RR), 256>>>(W1, w1hi, w1lo);
    wsplit_kernel<DOUT><<<dim3((128 * DOUT + 255) / 256, RR), 256>>>(W2, w2hi, w2lo);

    // layer-1 GEMM needs onorm (epilogue scaling); CSR build overlaps it
    cudaStreamWaitEvent(0, evNorm, 0);
    mma_gemm_kernel<128, 0><<<dim3((NN + 127) / 128, RR), 256, SMEM1>>>(x);

    // ---- join: aggregation needs CSR + inorm ----
    cudaStreamWaitEvent(0, evPre, 0);
    agg1_kernel<<<(NN * 32 + 255) / 256, 256>>>(b1);

    // layer 2
    mma_gemm_kernel<64, 1><<<dim3((NN + 127) / 128, RR), 256, SMEM2>>>(nullptr);
    agg2_kernel<<<(NN * 32 + 255) / 256, 256>>>(b2, out);
}

// round 15
// speedup vs baseline: 4.4536x; 1.2723x over previous
#include <cuda_runtime.h>
#include <cuda_bf16.h>
#include <cuda_fp16.h>
#include <cstdint>

#define RR   3
#define NN   50000
#define EE   200000
#define RN   (RR*NN)
#define RE   (RR*EE)
#define DIN  128
#define DHID 128
#define DOUT 64
#define NB   ((RN + 1023) / 1024)   // 147 scan blocks

// ---------------- scratch (device globals; no allocation allowed) ----------
__device__ int   g_deg_out[RN];
__device__ int   g_deg_in [RN];
__device__ float g_onorm  [RN];
__device__ float g_inorm  [RN];
__device__ int   g_rowptr [RN + 1];
__device__ int   g_pos    [RN];
__device__ int   g_colsrc [RE];
__device__ int   g_blocksum[NB];
__device__ int   g_blockoff[NB + 1];
__device__ __half g_Y1h[(size_t)RN * DHID];  // onorm-scaled transformed feats (fp16)
__device__ __half g_Hh [(size_t)NN * DHID];  // hidden after relu (fp16)
__device__ __half g_Y2h[(size_t)RN * DOUT];
__device__ __half g_W1T[RR * DHID * DIN];    // W1^T [r][n][k], fp16
__device__ __half g_W2T[RR * DOUT * DHID];   // W2^T [r][n][k], fp16

// ---------------- ptx helpers ------------------------------------------------
__device__ __forceinline__ uint32_t smem_u32(const void* p) {
    uint32_t a;
    asm("{ .reg .u64 t; cvta.to.shared.u64 t, %1; cvt.u32.u64 %0, t; }"
        : "=r"(a) : "l"(p));
    return a;
}
__device__ __forceinline__ void ldsm_x4(uint32_t& r0, uint32_t& r1,
                                        uint32_t& r2, uint32_t& r3, uint32_t a) {
    asm volatile("ldmatrix.sync.aligned.m8n8.x4.shared.b16 {%0,%1,%2,%3}, [%4];"
                 : "=r"(r0), "=r"(r1), "=r"(r2), "=r"(r3) : "r"(a));
}
__device__ __forceinline__ void ldsm_x2(uint32_t& r0, uint32_t& r1, uint32_t a) {
    asm volatile("ldmatrix.sync.aligned.m8n8.x2.shared.b16 {%0,%1}, [%2];"
                 : "=r"(r0), "=r"(r1) : "r"(a));
}
__device__ __forceinline__ void mma_f16(float* d, const uint32_t* a,
                                        const uint32_t* b) {
    asm volatile(
        "mma.sync.aligned.m16n8k16.row.col.f32.f16.f16.f32 "
        "{%0,%1,%2,%3}, {%4,%5,%6,%7}, {%8,%9}, {%0,%1,%2,%3};"
        : "+f"(d[0]), "+f"(d[1]), "+f"(d[2]), "+f"(d[3])
        : "r"(a[0]), "r"(a[1]), "r"(a[2]), "r"(a[3]), "r"(b[0]), "r"(b[1]));
}
__device__ __forceinline__ uint32_t h2u(__half2 v) {
    return *reinterpret_cast<uint32_t*>(&v);
}

// ---------------- graph preprocessing ---------------------------------------
__global__ void zero_deg_kernel() {
    int i = blockIdx.x * blockDim.x + threadIdx.x;
    if (i < RN) { g_deg_out[i] = 0; g_deg_in[i] = 0; }
}

__global__ void count_deg_kernel(const int* __restrict__ src,
                                 const int* __restrict__ dst) {
    int e = blockIdx.x * blockDim.x + threadIdx.x;
    if (e >= EE) return;
    int r = blockIdx.y;
    int i = r * EE + e;
    atomicAdd(&g_deg_out[r * NN + src[i]], 1);
    atomicAdd(&g_deg_in [r * NN + dst[i]], 1);
}

__global__ void onorm_kernel() {
    int i = blockIdx.x * blockDim.x + threadIdx.x;
    if (i >= RN) return;
    int od = g_deg_out[i]; if (od < 1) od = 1;
    g_onorm[i] = rsqrtf((float)od);
}

__global__ void scan1_kernel() {
    __shared__ int sm[1024];
    const int t = threadIdx.x;
    const int i = blockIdx.x * 1024 + t;
    int v = (i < RN) ? g_deg_in[i] : 0;
    sm[t] = v;
    __syncthreads();
    #pragma unroll
    for (int off = 1; off < 1024; off <<= 1) {
        int u = (t >= off) ? sm[t - off] : 0;
        __syncthreads();
        sm[t] += u;
        __syncthreads();
    }
    if (i < RN) g_rowptr[i] = sm[t];
    if (t == 1023) g_blocksum[blockIdx.x] = sm[1023];
}

__global__ void scan2_kernel() {
    __shared__ int sm[256];
    const int t = threadIdx.x;
    int v = (t < NB) ? g_blocksum[t] : 0;
    sm[t] = v;
    __syncthreads();
    #pragma unroll
    for (int off = 1; off < 256; off <<= 1) {
        int u = (t >= off) ? sm[t - off] : 0;
        __syncthreads();
        sm[t] += u;
        __syncthreads();
    }
    if (t < NB) g_blockoff[t] = sm[t] - v;
    if (t == NB - 1) g_blockoff[NB] = sm[t];
}

// scan fixup + inorm (deg_in already in hand)
__global__ void scan3_kernel() {
    int i = blockIdx.x * blockDim.x + threadIdx.x;
    if (i == 0) g_rowptr[RN] = g_blockoff[NB];
    if (i >= RN) return;
    int d = g_deg_in[i];
    int excl = g_rowptr[i] - d + g_blockoff[i >> 10];
    g_rowptr[i] = excl;
    g_pos[i]    = excl;
    g_inorm[i]  = rsqrtf((float)(d < 1 ? 1 : d));
}

__global__ void fill_csr_kernel(const int* __restrict__ src,
                                const int* __restrict__ dst) {
    int e = blockIdx.x * blockDim.x + threadIdx.x;
    if (e >= EE) return;
    int r = blockIdx.y;
    int i = r * EE + e;
    int p = atomicAdd(&g_pos[r * NN + dst[i]], 1);
    g_colsrc[p] = src[i];
}

// transpose W to fp16: [r][K=128][Ndim] fp32 -> [r][Ndim][128] fp16
template <int Ndim>
__global__ void wtrans_kernel(const float* __restrict__ W,
                              __half* __restrict__ T) {
    int r = blockIdx.y;
    int i = blockIdx.x * 256 + threadIdx.x;
    if (i >= 128 * Ndim) return;
    int k = i / Ndim, n = i % Ndim;
    T[((size_t)r * Ndim + n) * 128 + k] =
        __float2half_rn(W[((size_t)r * 128 + k) * Ndim + n]);
}

// ---------------- HMMA fp16 GEMM: Y[r] = onorm_r ⊙ (A @ W[r]) ---------------
// A converted to fp16 into swizzled SMEM (layer 1 copies fp16 H directly);
// W^T fp16 same layout. Full K resident; 8 k-steps of ldmatrix + mma.sync.
// Epilogue scales rows by onorm and stores fp16. 2 CTAs/SM.
template <int N, int LAYER>
__global__ void __launch_bounds__(256, 2)
mma_gemm_kernel(const float* __restrict__ xin) {
    extern __shared__ char smem[];
    const __half* WT = (LAYER == 0) ? g_W1T : g_W2T;
    __half* Y = (LAYER == 0) ? g_Y1h : g_Y2h;

    constexpr int OFF_A = 0;                 // 128 rows x 256B = 32KB
    constexpr int OFF_B = 128 * 256;         // N rows x 256B

    const int t = threadIdx.x;
    const int r = blockIdx.y;
    const int row0 = blockIdx.x * 128;

    // ---- B: copy fp16 granules into swizzled SMEM ----
    {
        const uint4* bp = (const uint4*)(WT + (size_t)r * N * 128);
        #pragma unroll
        for (int i = t; i < N * 16; i += 256) {
            int n = i >> 4, g = i & 15;
            uint32_t off = n * 256 + ((g ^ (n & 7)) << 4);
            *(uint4*)(smem + OFF_B + off) = bp[i];
        }
    }
    // ---- A: layer0 = fp32->fp16 convert; layer1 = raw fp16 copy ----
    #pragma unroll
    for (int i = t; i < 128 * 16; i += 256) {
        int m = i >> 4, g = i & 15;
        int grow = row0 + m;
        uint4 packed = make_uint4(0u, 0u, 0u, 0u);
        if (grow < NN) {
            if (LAYER == 0) {
                const float4* ap = (const float4*)(xin + (size_t)grow * 128 + g * 8);
                float4 v0 = ap[0], v1 = ap[1];
                packed = make_uint4(h2u(__floats2half2_rn(v0.x, v0.y)),
                                    h2u(__floats2half2_rn(v0.z, v0.w)),
                                    h2u(__floats2half2_rn(v1.x, v1.y)),
                                    h2u(__floats2half2_rn(v1.z, v1.w)));
            } else {
                packed = *(const uint4*)(g_Hh + (size_t)grow * 128 + g * 8);
            }
        }
        uint32_t off = m * 256 + ((g ^ (m & 7)) << 4);
        *(uint4*)(smem + OFF_A + off) = packed;
    }
    __syncthreads();

    // ---- warp tiling ----
    constexpr int WM = (N == 128) ? 64 : 32;    // warp M tile
    constexpr int WN = 32;                      // warp N tile
    constexpr int WX = N / WN;                  // warps along N
    constexpr int MI = WM / 16, NI = WN / 8;
    const int wid = t >> 5, lane = t & 31;
    const int wm0 = (wid / WX) * WM;
    const int wn0 = (wid % WX) * WN;

    float acc[MI][NI][4];
    #pragma unroll
    for (int mi = 0; mi < MI; mi++)
        #pragma unroll
        for (int ni = 0; ni < NI; ni++)
            #pragma unroll
            for (int q = 0; q < 4; q++) acc[mi][ni][q] = 0.f;

    const uint32_t sbase = smem_u32(smem);
    const int a_row = (lane & 15);
    const int a_kg  = (lane >> 4);
    const int b_n   = (lane & 7);
    const int b_kg  = ((lane >> 3) & 1);

    #pragma unroll
    for (int ks = 0; ks < 8; ks++) {
        uint32_t ah[MI][4];
        #pragma unroll
        for (int mi = 0; mi < MI; mi++) {
            int row = wm0 + mi * 16 + a_row;
            int kg  = ks * 2 + a_kg;
            uint32_t off = row * 256 + ((kg ^ (row & 7)) << 4);
            ldsm_x4(ah[mi][0], ah[mi][1], ah[mi][2], ah[mi][3],
                    sbase + OFF_A + off);
        }
        uint32_t bh[NI][2];
        #pragma unroll
        for (int ni = 0; ni < NI; ni++) {
            int n  = wn0 + ni * 8 + b_n;
            int kg = ks * 2 + b_kg;
            uint32_t off = n * 256 + ((kg ^ (n & 7)) << 4);
            ldsm_x2(bh[ni][0], bh[ni][1], sbase + OFF_B + off);
        }
        #pragma unroll
        for (int mi = 0; mi < MI; mi++)
            #pragma unroll
            for (int ni = 0; ni < NI; ni++)
                mma_f16(acc[mi][ni], ah[mi], bh[ni]);
    }

    // ---- epilogue: scale rows by onorm, write fp16 Y ----
    #pragma unroll
    for (int mi = 0; mi < MI; mi++) {
        int m0 = row0 + wm0 + mi * 16 + (lane >> 2);
        float on0 = (m0 < NN)     ? g_onorm[r * NN + m0]     : 0.f;
        float on1 = (m0 + 8 < NN) ? g_onorm[r * NN + m0 + 8] : 0.f;
        #pragma unroll
        for (int ni = 0; ni < NI; ni++) {
            int n = wn0 + ni * 8 + 2 * (lane & 3);
            if (m0 < NN)
                *(__half2*)&Y[((size_t)r * NN + m0) * N + n] =
                    __floats2half2_rn(acc[mi][ni][0] * on0, acc[mi][ni][1] * on0);
            if (m0 + 8 < NN)
                *(__half2*)&Y[((size_t)r * NN + m0 + 8) * N + n] =
                    __floats2half2_rn(acc[mi][ni][2] * on1, acc[mi][ni][3] * on1);
        }
    }
}

// ---------------- aggregation (gather via CSR, onorm pre-folded) ------------
__global__ void agg1_kernel(const float* __restrict__ b1) {
    int gt   = blockIdx.x * blockDim.x + threadIdx.x;
    int n    = gt >> 5;
    int lane = gt & 31;
    if (n >= NN) return;

    float4 acc = make_float4(0.f, 0.f, 0.f, 0.f);
    #pragma unroll
    for (int r = 0; r < RR; r++) {
        int key = r * NN + n;
        int beg = g_rowptr[key];
        int end = g_rowptr[key + 1];
        const __half* Yr = g_Y1h + (size_t)r * NN * DHID;
        float4 s = make_float4(0.f, 0.f, 0.f, 0.f);
        int j = beg;
        for (; j + 1 < end; j += 2) {
            int sn0 = g_colsrc[j];
            int sn1 = g_colsrc[j + 1];
            uint2 u0 = *(const uint2*)&Yr[(size_t)sn0 * DHID + lane * 4];
            uint2 u1 = *(const uint2*)&Yr[(size_t)sn1 * DHID + lane * 4];
            float2 a0 = __half22float2(*reinterpret_cast<const __half2*>(&u0.x));
            float2 a1 = __half22float2(*reinterpret_cast<const __half2*>(&u0.y));
            float2 c0 = __half22float2(*reinterpret_cast<const __half2*>(&u1.x));
            float2 c1 = __half22float2(*reinterpret_cast<const __half2*>(&u1.y));
            s.x += a0.x + c0.x; s.y += a0.y + c0.y;
            s.z += a1.x + c1.x; s.w += a1.y + c1.y;
        }
        if (j < end) {
            int sn = g_colsrc[j];
            uint2 u = *(const uint2*)&Yr[(size_t)sn * DHID + lane * 4];
            float2 a0 = __half22float2(*reinterpret_cast<const __half2*>(&u.x));
            float2 a1 = __half22float2(*reinterpret_cast<const __half2*>(&u.y));
            s.x += a0.x; s.y += a0.y; s.z += a1.x; s.w += a1.y;
        }
        float inn = g_inorm[key];
        acc.x += inn * s.x; acc.y += inn * s.y;
        acc.z += inn * s.z; acc.w += inn * s.w;
    }
    int col = lane * 4;
    acc.x += b1[col + 0] + b1[DHID + col + 0] + b1[2 * DHID + col + 0];
    acc.y += b1[col + 1] + b1[DHID + col + 1] + b1[2 * DHID + col + 1];
    acc.z += b1[col + 2] + b1[DHID + col + 2] + b1[2 * DHID + col + 2];
    acc.w += b1[col + 3] + b1[DHID + col + 3] + b1[2 * DHID + col + 3];
    acc.x = fmaxf(acc.x, 0.f); acc.y = fmaxf(acc.y, 0.f);
    acc.z = fmaxf(acc.z, 0.f); acc.w = fmaxf(acc.w, 0.f);
    __half2 p0 = __floats2half2_rn(acc.x, acc.y);
    __half2 p1 = __floats2half2_rn(acc.z, acc.w);
    *(uint2*)&g_Hh[(size_t)n * DHID + col] =
        make_uint2(*(uint32_t*)&p0, *(uint32_t*)&p1);
}

__global__ void agg2_kernel(const float* __restrict__ b2,
                            float* __restrict__ out) {
    int gt   = blockIdx.x * blockDim.x + threadIdx.x;
    int n    = gt >> 5;
    int lane = gt & 31;
    if (n >= NN) return;

    float2 acc = make_float2(0.f, 0.f);
    #pragma unroll
    for (int r = 0; r < RR; r++) {
        int key = r * NN + n;
        int beg = g_rowptr[key];
        int end = g_rowptr[key + 1];
        const __half* Yr = g_Y2h + (size_t)r * NN * DOUT;
        float2 s = make_float2(0.f, 0.f);
        int j = beg;
        for (; j + 1 < end; j += 2) {
            int sn0 = g_colsrc[j];
            int sn1 = g_colsrc[j + 1];
            uint32_t u0 = *(const uint32_t*)&Yr[(size_t)sn0 * DOUT + lane * 2];
            uint32_t u1 = *(const uint32_t*)&Yr[(size_t)sn1 * DOUT + lane * 2];
            float2 f0 = __half22float2(*reinterpret_cast<const __half2*>(&u0));
            float2 f1 = __half22float2(*reinterpret_cast<const __half2*>(&u1));
            s.x += f0.x + f1.x; s.y += f0.y + f1.y;
        }
        if (j < end) {
            int sn = g_colsrc[j];
            uint32_t u = *(const uint32_t*)&Yr[(size_t)sn * DOUT + lane * 2];
            float2 f = __half22float2(*reinterpret_cast<const __half2*>(&u));
            s.x += f.x; s.y += f.y;
        }
        float inn = g_inorm[key];
        acc.x += inn * s.x; acc.y += inn * s.y;
    }
    int col = lane * 2;
    acc.x += b2[col + 0] + b2[DOUT + col + 0] + b2[2 * DOUT + col + 0];
    acc.y += b2[col + 1] + b2[DOUT + col + 1] + b2[2 * DOUT + col + 1];
    *(float2*)&out[(size_t)n * DOUT + col] = acc;
}

// ---------------- launch -----------------------------------------------------
extern "C" void kernel_launch(void* const* d_in, const int* in_sizes, int n_in,
                              void* d_out, int out_size) {
    const float* x   = (const float*)d_in[0];
    const float* W1  = (const float*)d_in[1];
    const float* b1  = (const float*)d_in[2];
    const float* W2  = (const float*)d_in[3];
    const float* b2  = (const float*)d_in[4];
    const int*   src = (const int*)d_in[5];
    const int*   dst = (const int*)d_in[6];
    float*       out = (float*)d_out;

    __half *w1t, *w2t;
    cudaGetSymbolAddress((void**)&w1t, g_W1T);
    cudaGetSymbolAddress((void**)&w2t, g_W2T);

    // one-time host resources (no device memory involved)
    static cudaStream_t s2 = nullptr;
    static cudaEvent_t  evFork = nullptr, evNorm = nullptr, evPre = nullptr;
    if (s2 == nullptr) {
        cudaStreamCreateWithFlags(&s2, cudaStreamNonBlocking);
        cudaEventCreateWithFlags(&evFork, cudaEventDisableTiming);
        cudaEventCreateWithFlags(&evNorm, cudaEventDisableTiming);
        cudaEventCreateWithFlags(&evPre,  cudaEventDisableTiming);
    }

    const int SMEM1 = (128 + 128) * 256;   // 65536
    const int SMEM2 = (128 +  64) * 256;   // 49152
    cudaFuncSetAttribute(mma_gemm_kernel<128, 0>,
                         cudaFuncAttributeMaxDynamicSharedMemorySize, SMEM1);
    cudaFuncSetAttribute(mma_gemm_kernel<64, 1>,
                         cudaFuncAttributeMaxDynamicSharedMemorySize, SMEM2);

    // ---- fork: graph preprocessing on side stream ----
    cudaEventRecord(evFork, 0);
    cudaStreamWaitEvent(s2, evFork, 0);
    zero_deg_kernel <<<(RN + 255) / 256, 256, 0, s2>>>();
    count_deg_kernel<<<dim3((EE + 255) / 256, RR), 256, 0, s2>>>(src, dst);
    onorm_kernel    <<<(RN + 255) / 256, 256, 0, s2>>>();
    cudaEventRecord(evNorm, s2);                     // onorm ready for GEMM1
    scan1_kernel    <<<NB, 1024, 0, s2>>>();
    scan2_kernel    <<<1, 256, 0, s2>>>();
    scan3_kernel    <<<(RN + 255) / 256, 256, 0, s2>>>();  // + inorm
    fill_csr_kernel <<<dim3((EE + 255) / 256, RR), 256, 0, s2>>>(src, dst);
    cudaEventRecord(evPre, s2);

    // ---- main stream: weight transpose overlaps count/norm ----
    wtrans_kernel<DHID><<<dim3((128 * DHID + 255) / 256, RR), 256>>>(W1, w1t);
    wtrans_kernel<DOUT><<<dim3((128 * DOUT + 255) / 256, RR), 256>>>(W2, w2t);

    // layer-1 GEMM needs onorm (epilogue scaling); CSR build overlaps it
    cudaStreamWaitEvent(0, evNorm, 0);
    mma_gemm_kernel<128, 0><<<dim3((NN + 127) / 128, RR), 256, SMEM1>>>(x);

    // ---- join: aggregation needs CSR + inorm ----
    cudaStreamWaitEvent(0, evPre, 0);
    agg1_kernel<<<(NN * 32 + 255) / 256, 256>>>(b1);

    // layer 2
    mma_gemm_kernel<64, 1><<<dim3((NN + 127) / 128, RR), 256, SMEM2>>>(nullptr);
    agg2_kernel<<<(NN * 32 + 255) / 256, 256>>>(b2, out);
}